// round 7
// baseline (speedup 1.0000x reference)
#include <cuda_runtime.h>
#include <cuda_bf16.h>
#include <cuda_fp16.h>
#include <cstdint>

#define N_NODES 100000
#define N_EDGES 640000
#define D 128
#define RS 256                               // interleaved row stride (hi|lo)
#define NB_SCAN ((N_NODES + 1023) / 1024)    // 98

typedef __nv_bfloat16 bf16;
typedef __nv_bfloat162 bf162;

// ---------------- scratch (device globals: no allocation allowed) ----------
__device__ __align__(16) __half g_pa16[N_NODES * D];
__device__ __align__(16) __half g_pb16[N_NODES * D];
// interleaved node tensors: row = [128 hi | 128 lo] bf16
__device__ __align__(16) bf16 g_x[N_NODES * RS];
__device__ __align__(16) bf16 g_m[N_NODES * RS];
__device__ __align__(16) bf16 g_h1[N_NODES * RS];
__device__ __align__(16) bf16 g_h2[N_NODES * RS];
// packed weights [K][N]: rows [Ws1|Wn1|Ws2|Wn2 | comp_pa(256) | comp_pb(256)]
__device__ __align__(16) bf16 g_wh[1024 * D];
__device__ __align__(16) bf16 g_wl[1024 * D];
__device__ float g_bc[2 * D];                // composed predictor biases
// CSR
__device__ int g_cnt[N_NODES];
__device__ int g_rowptr[N_NODES + 1];
__device__ int g_csr[N_EDGES];
__device__ int g_bsum[NB_SCAN];
__device__ int g_boff[NB_SCAN];

// ---------------- CSR construction ----------------------------------------
__global__ void k_zero_cnt() {
    int i = blockIdx.x * blockDim.x + threadIdx.x;
    if (i < N_NODES) g_cnt[i] = 0;
}
__global__ void k_hist(const int* __restrict__ dst) {
    int e = blockIdx.x * blockDim.x + threadIdx.x;
    if (e < N_EDGES) atomicAdd(&g_cnt[dst[e]], 1);
}
__global__ void k_blockscan() {
    __shared__ int sh[1024];
    int tid = threadIdx.x;
    int i = blockIdx.x * 1024 + tid;
    int v = (i < N_NODES) ? g_cnt[i] : 0;
    sh[tid] = v;
    __syncthreads();
    for (int o = 1; o < 1024; o <<= 1) {
        int t = (tid >= o) ? sh[tid - o] : 0;
        __syncthreads();
        sh[tid] += t;
        __syncthreads();
    }
    if (i < N_NODES) g_rowptr[i] = sh[tid] - v;
    if (tid == 1023) g_bsum[blockIdx.x] = sh[1023];
}
__global__ void k_scan_bsum() {
    __shared__ int sh[128];
    int t = threadIdx.x;
    int v = (t < NB_SCAN) ? g_bsum[t] : 0;
    sh[t] = v;
    __syncthreads();
    for (int o = 1; o < 128; o <<= 1) {
        int u = (t >= o) ? sh[t - o] : 0;
        __syncthreads();
        sh[t] += u;
        __syncthreads();
    }
    if (t < NB_SCAN) g_boff[t] = sh[t] - v;
    if (t == NB_SCAN - 1) g_rowptr[N_NODES] = sh[t];
}
__global__ void k_addoff() {
    int i = blockIdx.x * blockDim.x + threadIdx.x;
    if (i < N_NODES) {
        g_rowptr[i] += g_boff[i >> 10];
        g_cnt[i] = 0;
    }
}
__global__ void k_place(const int* __restrict__ src, const int* __restrict__ dst) {
    int e = blockIdx.x * blockDim.x + threadIdx.x;
    if (e < N_EDGES) {
        int d = dst[e];
        int slot = g_rowptr[d] + atomicAdd(&g_cnt[d], 1);
        g_csr[slot] = src[e];
    }
}

// ---------------- conversions ----------------------------------------------
__device__ __forceinline__ void split_bf16(float v, bf16& h, bf16& l) {
    h = __float2bfloat16_rn(v);
    l = __float2bfloat16_rn(v - __bfloat162float(h));
}

// x fp32 -> interleaved hi/lo rows
__global__ void k_cvt4(const float* __restrict__ in, bf16* __restrict__ o, int n4) {
    int i = blockIdx.x * blockDim.x + threadIdx.x;
    if (i >= n4) return;
    float4 v = ((const float4*)in)[i];
    bf16 hx, hy, hz, hw, lx, ly, lz, lw;
    split_bf16(v.x, hx, lx); split_bf16(v.y, hy, ly);
    split_bf16(v.z, hz, lz); split_bf16(v.w, hw, lw);
    int row = i >> 5, d4 = (i & 31) * 4;
    bf162* ph = (bf162*)&o[row * RS + d4];
    bf162* pl = (bf162*)&o[row * RS + 128 + d4];
    ph[0] = __halves2bfloat162(hx, hy); ph[1] = __halves2bfloat162(hz, hw);
    pl[0] = __halves2bfloat162(lx, ly); pl[1] = __halves2bfloat162(lz, lw);
}

// layer 1/2 weights -> rows 0..511
__global__ void k_cvt_w(const float* Ws1, const float* Wn1,
                        const float* Ws2, const float* Wn2) {
    int i = blockIdx.x * blockDim.x + threadIdx.x;   // 0 .. 512*128-1
    if (i >= 512 * D) return;
    int row = i >> 7, col = i & 127;
    const float* s; int lr;
    if      (row < 128)  { s = Ws1; lr = row; }
    else if (row < 256)  { s = Wn1; lr = row - 128; }
    else if (row < 384)  { s = Ws2; lr = row - 256; }
    else                 { s = Wn2; lr = row - 384; }
    float v = s[lr * D + col];
    bf16 h, l; split_bf16(v, h, l);
    g_wh[i] = h; g_wl[i] = l;
}

// composed predictor weights: rows 512..1023
// p0: Ws3@Wp1_top -> 512+i ; p1: Wn3@Wp1_top -> 640+i
// p2: Ws3@Wp1_bot -> 768+i ; p3: Wn3@Wp1_bot -> 896+i
__global__ void k_compose(const float* __restrict__ Ws3, const float* __restrict__ Wn3,
                          const float* __restrict__ Wp1) {
    int p = blockIdx.x >> 7, i = blockIdx.x & 127;
    const float* X = (p & 1) ? Wn3 : Ws3;
    const float* Y = Wp1 + ((p >> 1) ? 128 * D : 0);
    __shared__ float xr[128];
    int n = threadIdx.x;
    xr[n] = X[i * D + n];
    __syncthreads();
    float s = 0.f;
    #pragma unroll 8
    for (int k = 0; k < 128; k++) s += xr[k] * Y[k * D + n];
    int dst = ((p < 2) ? 512 : 768) + (p & 1) * 128 + i;
    bf16 h, l; split_bf16(s, h, l);
    g_wh[dst * D + n] = h; g_wl[dst * D + n] = l;
}
__global__ void k_bias_comp(const float* __restrict__ b3, const float* __restrict__ Wp1,
                            const float* __restrict__ bp1) {
    int n = threadIdx.x, half = blockIdx.x;
    float s = (half == 0) ? bp1[n] : 0.f;
    for (int j = 0; j < 128; j++) s += b3[j] * Wp1[(half * 128 + j) * D + n];
    g_bc[half * D + n] = s;
}

// ---------------- mean aggregation: interleaved rows, 1 LDG.128/edge/lane --
__global__ void k_agg(const bf16* __restrict__ xin) {
    int gw   = (blockIdx.x * blockDim.x + threadIdx.x) >> 5;
    int lane = threadIdx.x & 31;
    if (gw >= N_NODES) return;
    int beg = g_rowptr[gw], end = g_rowptr[gw + 1];
    float acc[8];
    #pragma unroll
    for (int j = 0; j < 8; j++) acc[j] = 0.f;
    for (int e = beg; e < end; e++) {
        const uint4 v = *(const uint4*)&xin[(size_t)g_csr[e] * RS + lane * 8];
        float2 f0 = __bfloat1622float2(*(bf162*)&v.x);
        float2 f1 = __bfloat1622float2(*(bf162*)&v.y);
        float2 f2 = __bfloat1622float2(*(bf162*)&v.z);
        float2 f3 = __bfloat1622float2(*(bf162*)&v.w);
        acc[0] += f0.x; acc[1] += f0.y; acc[2] += f1.x; acc[3] += f1.y;
        acc[4] += f2.x; acc[5] += f2.y; acc[6] += f3.x; acc[7] += f3.y;
    }
    // combine hi-lane (values) + lo-lane (corrections): same dims at lane^16
    #pragma unroll
    for (int j = 0; j < 8; j++)
        acc[j] += __shfl_xor_sync(0xffffffffu, acc[j], 16);
    int deg = end - beg;
    float inv = 1.0f / (float)(deg > 1 ? deg : 1);
    bf16 hs[8], ls[8];
    #pragma unroll
    for (int j = 0; j < 8; j++) {
        float v = acc[j] * inv;
        split_bf16(v, hs[j], ls[j]);
    }
    uint4 out;
    bf162* op = (bf162*)&out;
    if (lane < 16) {
        op[0] = __halves2bfloat162(hs[0], hs[1]); op[1] = __halves2bfloat162(hs[2], hs[3]);
        op[2] = __halves2bfloat162(hs[4], hs[5]); op[3] = __halves2bfloat162(hs[6], hs[7]);
        *(uint4*)&g_m[(size_t)gw * RS + lane * 8] = out;
    } else {
        op[0] = __halves2bfloat162(ls[0], ls[1]); op[1] = __halves2bfloat162(ls[2], ls[3]);
        op[2] = __halves2bfloat162(ls[4], ls[5]); op[3] = __halves2bfloat162(ls[6], ls[7]);
        *(uint4*)&g_m[(size_t)gw * RS + 128 + (lane - 16) * 8] = out;
    }
}

// ---------------- tensor-core GEMM (512 thr, 16 warps, 3-stage) ------------
__device__ __forceinline__ void ldsm4(uint32_t& r0, uint32_t& r1, uint32_t& r2,
                                      uint32_t& r3, uint32_t addr) {
    asm volatile("ldmatrix.sync.aligned.m8n8.x4.shared.b16 {%0,%1,%2,%3}, [%4];"
                 : "=r"(r0), "=r"(r1), "=r"(r2), "=r"(r3) : "r"(addr));
}
__device__ __forceinline__ void ldsm4t(uint32_t& r0, uint32_t& r1, uint32_t& r2,
                                       uint32_t& r3, uint32_t addr) {
    asm volatile("ldmatrix.sync.aligned.m8n8.x4.trans.shared.b16 {%0,%1,%2,%3}, [%4];"
                 : "=r"(r0), "=r"(r1), "=r"(r2), "=r"(r3) : "r"(addr));
}
__device__ __forceinline__ void mma_bf16(float* c, const uint32_t* a, const uint32_t* b) {
    asm volatile(
        "mma.sync.aligned.m16n8k16.row.col.f32.bf16.bf16.f32 "
        "{%0,%1,%2,%3},{%4,%5,%6,%7},{%8,%9},{%0,%1,%2,%3};"
        : "+f"(c[0]), "+f"(c[1]), "+f"(c[2]), "+f"(c[3])
        : "r"(a[0]), "r"(a[1]), "r"(a[2]), "r"(a[3]), "r"(b[0]), "r"(b[1]));
}
__device__ __forceinline__ void cp16(uint32_t s, const void* g, bool p) {
    asm volatile("cp.async.cg.shared.global [%0], [%1], 16, %2;"
                 :: "r"(s), "l"(g), "r"(p ? 16 : 0));
}

#define A_STRIDE 80u
#define B_STRIDE 272u
#define A_BYTES (128u * A_STRIDE)            // 10240
#define B_BYTES (32u * B_STRIDE)             // 8704
#define STAGE (2u * A_BYTES + 2u * B_BYTES)  // 37888
#define GEMM_SMEM (3 * STAGE)                // 113664

// out[M,128] = (A1|A2)[M,K=256] @ W[K,128] + bias ; 3-term bf16 split.
// A1/A2 interleaved rows (hi @ +0, lo @ +128, stride RS).
// If out16a: gridDim.y==2 -> y==1 selects W+256 rows, bias+128, out16b.
__global__ __launch_bounds__(512, 1) void k_gemm_tc(
    const bf16* __restrict__ A1, const bf16* __restrict__ A2,
    const bf16* __restrict__ Wh, const bf16* __restrict__ Wl,
    const float* __restrict__ bias,
    bf16* __restrict__ outp,
    __half* __restrict__ out16a, __half* __restrict__ out16b,
    int M, int K)
{
    extern __shared__ char smdyn[];
    uint32_t base = (uint32_t)__cvta_generic_to_shared(smdyn);

    __half* o16 = out16a;
    if (out16a && blockIdx.y == 1) {
        Wh += 256 * D; Wl += 256 * D; bias += 128; o16 = out16b;
    }

    int tid = threadIdx.x;
    int wid = tid >> 5, lane = tid & 31;
    int warp_m = (wid >> 2) * 32;
    int warp_n = (wid & 3) * 32;
    int m0 = blockIdx.x * 128;
    int nch = K / 32;

    float c[2][4][4];
    #pragma unroll
    for (int i = 0; i < 2; i++)
        #pragma unroll
        for (int j = 0; j < 4; j++)
            #pragma unroll
            for (int q = 0; q < 4; q++) c[i][j][q] = 0.f;

    auto load_chunk = [&](int ch) {
        uint32_t st = base + (uint32_t)(ch % 3) * STAGE;
        int kb = ch * 32;
        const bf16* A = (kb < 128) ? A1 : A2;
        int ac = kb & 127;
        {   // A: 512 items (r, seg)
            int r = tid >> 2, seg = tid & 3;
            uint32_t so = (uint32_t)r * A_STRIDE + (uint32_t)seg * 16u;
            bool p = (m0 + r) < M;
            int rr = p ? (m0 + r) : 0;
            size_t go = (size_t)rr * RS + ac + seg * 8;
            cp16(st + so,           A + go, p);          // hi
            cp16(st + A_BYTES + so, A + go + 128, p);    // lo
        }
        {   // B: 512 items (r, seg)
            int r = tid >> 4, seg = tid & 15;
            uint32_t so = (uint32_t)r * B_STRIDE + (uint32_t)seg * 16u;
            size_t go = (size_t)(kb + r) * D + seg * 8;
            cp16(st + 2u * A_BYTES + so,           Wh + go, true);
            cp16(st + 2u * A_BYTES + B_BYTES + so, Wl + go, true);
        }
        asm volatile("cp.async.commit_group;" ::: "memory");
    };

    load_chunk(0);
    load_chunk(1);

    int lr = (lane & 7) + 8 * ((lane >> 3) & 1);
    int lc = 8 * (lane >> 4);

    for (int ch = 0; ch < nch; ch++) {
        if (ch + 1 < nch) {
            asm volatile("cp.async.wait_group 1;" ::: "memory");
        } else {
            asm volatile("cp.async.wait_group 0;" ::: "memory");
        }
        __syncthreads();
        if (ch + 2 < nch) load_chunk(ch + 2);

        uint32_t st   = base + (uint32_t)(ch % 3) * STAGE;
        uint32_t ah_b = st;
        uint32_t al_b = st + A_BYTES;
        uint32_t bh_b = st + 2u * A_BYTES;
        uint32_t bl_b = bh_b + B_BYTES;

        #pragma unroll
        for (int ks = 0; ks < 2; ks++) {
            int k0 = ks * 16;
            uint32_t ah[2][4], al_[2][4];
            #pragma unroll
            for (int mi = 0; mi < 2; mi++) {
                uint32_t ro = (uint32_t)(warp_m + mi * 16 + lr) * A_STRIDE
                            + (uint32_t)(k0 + lc) * 2u;
                ldsm4(ah[mi][0], ah[mi][1], ah[mi][2], ah[mi][3], ah_b + ro);
                ldsm4(al_[mi][0], al_[mi][1], al_[mi][2], al_[mi][3], al_b + ro);
            }
            uint32_t bh[4][2], bl[4][2];
            #pragma unroll
            for (int njp = 0; njp < 2; njp++) {
                uint32_t ro = (uint32_t)(k0 + lr) * B_STRIDE
                            + (uint32_t)(warp_n + njp * 16 + lc) * 2u;
                uint32_t r0, r1, r2, r3;
                ldsm4t(r0, r1, r2, r3, bh_b + ro);
                bh[2 * njp][0] = r0;     bh[2 * njp][1] = r1;
                bh[2 * njp + 1][0] = r2; bh[2 * njp + 1][1] = r3;
                ldsm4t(r0, r1, r2, r3, bl_b + ro);
                bl[2 * njp][0] = r0;     bl[2 * njp][1] = r1;
                bl[2 * njp + 1][0] = r2; bl[2 * njp + 1][1] = r3;
            }
            #pragma unroll
            for (int mi = 0; mi < 2; mi++)
                #pragma unroll
                for (int nj = 0; nj < 4; nj++) {
                    mma_bf16(c[mi][nj], ah[mi], bh[nj]);
                    mma_bf16(c[mi][nj], ah[mi], bl[nj]);
                    mma_bf16(c[mi][nj], al_[mi], bh[nj]);
                }
        }
    }

    // epilogue
    #pragma unroll
    for (int mi = 0; mi < 2; mi++) {
        #pragma unroll
        for (int nj = 0; nj < 4; nj++) {
            int row0 = m0 + warp_m + mi * 16 + (lane >> 2);
            int col  = warp_n + nj * 8 + (lane & 3) * 2;
            float b0 = bias ? bias[col] : 0.f;
            float b1 = bias ? bias[col + 1] : 0.f;
            #pragma unroll
            for (int h = 0; h < 2; h++) {
                int row = row0 + 8 * h;
                if (row < M) {
                    float v0 = c[mi][nj][2 * h]     + b0;
                    float v1 = c[mi][nj][2 * h + 1] + b1;
                    if (o16) {
                        *(__half2*)&o16[(size_t)row * D + col] =
                            __floats2half2_rn(v0, v1);
                    } else {
                        bf16 h0, l0, h1, l1;
                        split_bf16(v0, h0, l0); split_bf16(v1, h1, l1);
                        *(bf162*)&outp[(size_t)row * RS + col] = __halves2bfloat162(h0, h1);
                        *(bf162*)&outp[(size_t)row * RS + 128 + col] = __halves2bfloat162(l0, l1);
                    }
                }
            }
        }
    }
}

// ---------------- edge scoring (fp16 projections) ---------------------------
__global__ void k_edge(const int* __restrict__ s1, const int* __restrict__ d1,
                       const int* __restrict__ s2, const int* __restrict__ d2,
                       const float* __restrict__ Wp2, const float* __restrict__ bp2,
                       float* __restrict__ out)
{
    int gw   = (blockIdx.x * blockDim.x + threadIdx.x) >> 5;
    int lane = threadIdx.x & 31;
    if (gw >= 2 * N_EDGES) return;
    int ss, dd;
    if (gw < N_EDGES) { ss = s1[gw]; dd = d1[gw]; }
    else              { ss = s2[gw - N_EDGES]; dd = d2[gw - N_EDGES]; }

    uint2 av = *(const uint2*)&g_pa16[(size_t)ss * D + lane * 4];
    uint2 bv = *(const uint2*)&g_pb16[(size_t)dd * D + lane * 4];
    float2 a0 = __half22float2(*(__half2*)&av.x);
    float2 a1 = __half22float2(*(__half2*)&av.y);
    float2 b0 = __half22float2(*(__half2*)&bv.x);
    float2 b1 = __half22float2(*(__half2*)&bv.y);
    float4 w = *(const float4*)&Wp2[lane * 4];

    float p = fmaxf(a0.x + b0.x, 0.f) * w.x
            + fmaxf(a0.y + b0.y, 0.f) * w.y
            + fmaxf(a1.x + b1.x, 0.f) * w.z
            + fmaxf(a1.y + b1.y, 0.f) * w.w;
    #pragma unroll
    for (int o = 16; o > 0; o >>= 1) p += __shfl_xor_sync(0xffffffffu, p, o);
    if (lane == 0) out[gw] = p + bp2[0];
}

// ---------------- launch ----------------------------------------------------
extern "C" void kernel_launch(void* const* d_in, const int* in_sizes, int n_in,
                              void* d_out, int out_size)
{
    const float* x    = (const float*)d_in[0];
    const int*   src  = (const int*)d_in[1];
    const int*   dst  = (const int*)d_in[2];
    const int*   nsrc = (const int*)d_in[3];
    const int*   ndst = (const int*)d_in[4];
    const float* Ws1 = (const float*)d_in[5],  *Wn1 = (const float*)d_in[6],  *b1 = (const float*)d_in[7];
    const float* Ws2 = (const float*)d_in[8],  *Wn2 = (const float*)d_in[9],  *b2 = (const float*)d_in[10];
    const float* Ws3 = (const float*)d_in[11], *Wn3 = (const float*)d_in[12], *b3 = (const float*)d_in[13];
    const float* Wp1 = (const float*)d_in[14], *bp1 = (const float*)d_in[15];
    const float* Wp2 = (const float*)d_in[16], *bp2 = (const float*)d_in[17];
    float* out = (float*)d_out;

    __half *p_pa16, *p_pb16;
    bf16 *p_x, *p_m, *p_h1, *p_h2, *p_wh, *p_wl;
    float* p_bc;
    cudaGetSymbolAddress((void**)&p_pa16, g_pa16);
    cudaGetSymbolAddress((void**)&p_pb16, g_pb16);
    cudaGetSymbolAddress((void**)&p_x, g_x);
    cudaGetSymbolAddress((void**)&p_m, g_m);
    cudaGetSymbolAddress((void**)&p_h1, g_h1);
    cudaGetSymbolAddress((void**)&p_h2, g_h2);
    cudaGetSymbolAddress((void**)&p_wh, g_wh);
    cudaGetSymbolAddress((void**)&p_wl, g_wl);
    cudaGetSymbolAddress((void**)&p_bc, g_bc);

    cudaFuncSetAttribute(k_gemm_tc, cudaFuncAttributeMaxDynamicSharedMemorySize,
                         GEMM_SMEM);

    // --- build CSR ---
    k_zero_cnt<<<(N_NODES + 255) / 256, 256>>>();
    k_hist<<<(N_EDGES + 255) / 256, 256>>>(dst);
    k_blockscan<<<NB_SCAN, 1024>>>();
    k_scan_bsum<<<1, 128>>>();
    k_addoff<<<(N_NODES + 255) / 256, 256>>>();
    k_place<<<(N_EDGES + 255) / 256, 256>>>(src, dst);

    // --- conversions + weight composition ---
    int n4 = N_NODES * D / 4;
    k_cvt4<<<(n4 + 255) / 256, 256>>>(x, p_x, n4);
    k_cvt_w<<<(512 * D + 255) / 256, 256>>>(Ws1, Wn1, Ws2, Wn2);
    k_compose<<<512, 128>>>(Ws3, Wn3, Wp1);
    k_bias_comp<<<2, 128>>>(b3, Wp1, bp1);

    const int aggBlocks  = (N_NODES * 32 + 255) / 256;
    const int gemmBlocks = (N_NODES + 127) / 128;

    // --- layer 1 ---
    k_agg<<<aggBlocks, 256>>>(p_x);
    k_gemm_tc<<<gemmBlocks, 512, GEMM_SMEM>>>(p_x, p_m, p_wh, p_wl, b1,
                                              p_h1, nullptr, nullptr, N_NODES, 256);
    // --- layer 2 ---
    k_agg<<<aggBlocks, 256>>>(p_h1);
    k_gemm_tc<<<gemmBlocks, 512, GEMM_SMEM>>>(p_h1, p_m, p_wh + 256 * D, p_wl + 256 * D, b2,
                                              p_h2, nullptr, nullptr, N_NODES, 256);
    // --- layer 3 + predictor (fused via composed weights; gridDim.y=2) ---
    k_agg<<<aggBlocks, 256>>>(p_h2);
    k_gemm_tc<<<dim3(gemmBlocks, 2), 512, GEMM_SMEM>>>(
                                              p_h2, p_m, p_wh + 512 * D, p_wl + 512 * D, p_bc,
                                              nullptr, p_pa16, p_pb16, N_NODES, 256);

    // --- edge scores ---
    k_edge<<<(2 * N_EDGES * 32 + 255) / 256, 256>>>(src, dst, nsrc, ndst, Wp2, bp2, out);
}

// round 8
// speedup vs baseline: 1.0999x; 1.0999x over previous
#include <cuda_runtime.h>
#include <cuda_bf16.h>
#include <cuda_fp16.h>
#include <cstdint>

#define N_NODES 100000
#define N_EDGES 640000
#define D 128
#define RS 256                               // interleaved row stride (hi|lo)
#define NB_SCAN ((N_NODES + 1023) / 1024)    // 98

typedef __nv_bfloat16 bf16;
typedef __nv_bfloat162 bf162;

// ---------------- scratch (device globals: no allocation allowed) ----------
__device__ __align__(16) __half g_pa16[N_NODES * D];
__device__ __align__(16) __half g_pb16[N_NODES * D];
// interleaved node tensors: row = [128 hi | 128 lo] bf16
__device__ __align__(16) bf16 g_x[N_NODES * RS];
__device__ __align__(16) bf16 g_m[N_NODES * RS];
__device__ __align__(16) bf16 g_h1[N_NODES * RS];
__device__ __align__(16) bf16 g_h2[N_NODES * RS];
// packed weights [K][N]: rows [Ws1|Wn1|Ws2|Wn2 | comp_pa(256) | comp_pb(256)]
__device__ __align__(16) bf16 g_wh[1024 * D];
__device__ __align__(16) bf16 g_wl[1024 * D];
__device__ float g_bc[2 * D];                // composed predictor biases
// CSR
__device__ int g_cnt[N_NODES];
__device__ int g_rowptr[N_NODES + 1];
__device__ int g_csr[N_EDGES];
__device__ int g_bsum[NB_SCAN];
__device__ int g_boff[NB_SCAN];

// ---------------- CSR construction ----------------------------------------
__global__ void k_zero_cnt() {
    int i = blockIdx.x * blockDim.x + threadIdx.x;
    if (i < N_NODES) g_cnt[i] = 0;
}
__global__ void k_hist(const int* __restrict__ dst) {
    int e = blockIdx.x * blockDim.x + threadIdx.x;
    if (e < N_EDGES) atomicAdd(&g_cnt[dst[e]], 1);
}
__global__ void k_blockscan() {
    __shared__ int sh[1024];
    int tid = threadIdx.x;
    int i = blockIdx.x * 1024 + tid;
    int v = (i < N_NODES) ? g_cnt[i] : 0;
    sh[tid] = v;
    __syncthreads();
    for (int o = 1; o < 1024; o <<= 1) {
        int t = (tid >= o) ? sh[tid - o] : 0;
        __syncthreads();
        sh[tid] += t;
        __syncthreads();
    }
    if (i < N_NODES) g_rowptr[i] = sh[tid] - v;
    if (tid == 1023) g_bsum[blockIdx.x] = sh[1023];
}
__global__ void k_scan_bsum() {
    __shared__ int sh[128];
    int t = threadIdx.x;
    int v = (t < NB_SCAN) ? g_bsum[t] : 0;
    sh[t] = v;
    __syncthreads();
    for (int o = 1; o < 128; o <<= 1) {
        int u = (t >= o) ? sh[t - o] : 0;
        __syncthreads();
        sh[t] += u;
        __syncthreads();
    }
    if (t < NB_SCAN) g_boff[t] = sh[t] - v;
    if (t == NB_SCAN - 1) g_rowptr[N_NODES] = sh[t];
}
__global__ void k_addoff() {
    int i = blockIdx.x * blockDim.x + threadIdx.x;
    if (i < N_NODES) {
        g_rowptr[i] += g_boff[i >> 10];
        g_cnt[i] = 0;
    }
}
__global__ void k_place(const int* __restrict__ src, const int* __restrict__ dst) {
    int e = blockIdx.x * blockDim.x + threadIdx.x;
    if (e < N_EDGES) {
        int d = dst[e];
        int slot = g_rowptr[d] + atomicAdd(&g_cnt[d], 1);
        g_csr[slot] = src[e];
    }
}

// ---------------- conversions ----------------------------------------------
__device__ __forceinline__ void split_bf16(float v, bf16& h, bf16& l) {
    h = __float2bfloat16_rn(v);
    l = __float2bfloat16_rn(v - __bfloat162float(h));
}

// x fp32 -> interleaved hi/lo rows
__global__ void k_cvt4(const float* __restrict__ in, bf16* __restrict__ o, int n4) {
    int i = blockIdx.x * blockDim.x + threadIdx.x;
    if (i >= n4) return;
    float4 v = ((const float4*)in)[i];
    bf16 hx, hy, hz, hw, lx, ly, lz, lw;
    split_bf16(v.x, hx, lx); split_bf16(v.y, hy, ly);
    split_bf16(v.z, hz, lz); split_bf16(v.w, hw, lw);
    int row = i >> 5, d4 = (i & 31) * 4;
    bf162* ph = (bf162*)&o[row * RS + d4];
    bf162* pl = (bf162*)&o[row * RS + 128 + d4];
    ph[0] = __halves2bfloat162(hx, hy); ph[1] = __halves2bfloat162(hz, hw);
    pl[0] = __halves2bfloat162(lx, ly); pl[1] = __halves2bfloat162(lz, lw);
}

// layer 1/2 weights -> rows 0..511
__global__ void k_cvt_w(const float* Ws1, const float* Wn1,
                        const float* Ws2, const float* Wn2) {
    int i = blockIdx.x * blockDim.x + threadIdx.x;   // 0 .. 512*128-1
    if (i >= 512 * D) return;
    int row = i >> 7, col = i & 127;
    const float* s; int lr;
    if      (row < 128)  { s = Ws1; lr = row; }
    else if (row < 256)  { s = Wn1; lr = row - 128; }
    else if (row < 384)  { s = Ws2; lr = row - 256; }
    else                 { s = Wn2; lr = row - 384; }
    float v = s[lr * D + col];
    bf16 h, l; split_bf16(v, h, l);
    g_wh[i] = h; g_wl[i] = l;
}

// composed predictor weights: rows 512..1023
// p0: Ws3@Wp1_top -> 512+i ; p1: Wn3@Wp1_top -> 640+i
// p2: Ws3@Wp1_bot -> 768+i ; p3: Wn3@Wp1_bot -> 896+i
__global__ void k_compose(const float* __restrict__ Ws3, const float* __restrict__ Wn3,
                          const float* __restrict__ Wp1) {
    int p = blockIdx.x >> 7, i = blockIdx.x & 127;
    const float* X = (p & 1) ? Wn3 : Ws3;
    const float* Y = Wp1 + ((p >> 1) ? 128 * D : 0);
    __shared__ float xr[128];
    int n = threadIdx.x;
    xr[n] = X[i * D + n];
    __syncthreads();
    float s = 0.f;
    #pragma unroll 8
    for (int k = 0; k < 128; k++) s += xr[k] * Y[k * D + n];
    int dst = ((p < 2) ? 512 : 768) + (p & 1) * 128 + i;
    bf16 h, l; split_bf16(s, h, l);
    g_wh[dst * D + n] = h; g_wl[dst * D + n] = l;
}
__global__ void k_bias_comp(const float* __restrict__ b3, const float* __restrict__ Wp1,
                            const float* __restrict__ bp1) {
    int n = threadIdx.x, half = blockIdx.x;
    float s = (half == 0) ? bp1[n] : 0.f;
    for (int j = 0; j < 128; j++) s += b3[j] * Wp1[(half * 128 + j) * D + n];
    g_bc[half * D + n] = s;
}

// ---------------- mean aggregation: interleaved rows, 1 LDG.128/edge/lane --
__global__ void k_agg(const bf16* __restrict__ xin) {
    int gw   = (blockIdx.x * blockDim.x + threadIdx.x) >> 5;
    int lane = threadIdx.x & 31;
    if (gw >= N_NODES) return;
    int beg = g_rowptr[gw], end = g_rowptr[gw + 1];
    float acc[8];
    #pragma unroll
    for (int j = 0; j < 8; j++) acc[j] = 0.f;
    for (int e = beg; e < end; e++) {
        const uint4 v = *(const uint4*)&xin[(size_t)g_csr[e] * RS + lane * 8];
        float2 f0 = __bfloat1622float2(*(bf162*)&v.x);
        float2 f1 = __bfloat1622float2(*(bf162*)&v.y);
        float2 f2 = __bfloat1622float2(*(bf162*)&v.z);
        float2 f3 = __bfloat1622float2(*(bf162*)&v.w);
        acc[0] += f0.x; acc[1] += f0.y; acc[2] += f1.x; acc[3] += f1.y;
        acc[4] += f2.x; acc[5] += f2.y; acc[6] += f3.x; acc[7] += f3.y;
    }
    // combine hi-lane (values) + lo-lane (corrections): same dims at lane^16
    #pragma unroll
    for (int j = 0; j < 8; j++)
        acc[j] += __shfl_xor_sync(0xffffffffu, acc[j], 16);
    int deg = end - beg;
    float inv = 1.0f / (float)(deg > 1 ? deg : 1);
    bf16 hs[8], ls[8];
    #pragma unroll
    for (int j = 0; j < 8; j++) {
        float v = acc[j] * inv;
        split_bf16(v, hs[j], ls[j]);
    }
    uint4 outv;
    bf162* op = (bf162*)&outv;
    if (lane < 16) {
        op[0] = __halves2bfloat162(hs[0], hs[1]); op[1] = __halves2bfloat162(hs[2], hs[3]);
        op[2] = __halves2bfloat162(hs[4], hs[5]); op[3] = __halves2bfloat162(hs[6], hs[7]);
        *(uint4*)&g_m[(size_t)gw * RS + lane * 8] = outv;
    } else {
        op[0] = __halves2bfloat162(ls[0], ls[1]); op[1] = __halves2bfloat162(ls[2], ls[3]);
        op[2] = __halves2bfloat162(ls[4], ls[5]); op[3] = __halves2bfloat162(ls[6], ls[7]);
        *(uint4*)&g_m[(size_t)gw * RS + 128 + (lane - 16) * 8] = outv;
    }
}

// ---------------- tensor-core GEMM (round-6 cfg: 256 thr, 2 CTA/SM) --------
__device__ __forceinline__ void ldsm4(uint32_t& r0, uint32_t& r1, uint32_t& r2,
                                      uint32_t& r3, uint32_t addr) {
    asm volatile("ldmatrix.sync.aligned.m8n8.x4.shared.b16 {%0,%1,%2,%3}, [%4];"
                 : "=r"(r0), "=r"(r1), "=r"(r2), "=r"(r3) : "r"(addr));
}
__device__ __forceinline__ void ldsm4t(uint32_t& r0, uint32_t& r1, uint32_t& r2,
                                       uint32_t& r3, uint32_t addr) {
    asm volatile("ldmatrix.sync.aligned.m8n8.x4.trans.shared.b16 {%0,%1,%2,%3}, [%4];"
                 : "=r"(r0), "=r"(r1), "=r"(r2), "=r"(r3) : "r"(addr));
}
__device__ __forceinline__ void mma_bf16(float* c, const uint32_t* a, const uint32_t* b) {
    asm volatile(
        "mma.sync.aligned.m16n8k16.row.col.f32.bf16.bf16.f32 "
        "{%0,%1,%2,%3},{%4,%5,%6,%7},{%8,%9},{%0,%1,%2,%3};"
        : "+f"(c[0]), "+f"(c[1]), "+f"(c[2]), "+f"(c[3])
        : "r"(a[0]), "r"(a[1]), "r"(a[2]), "r"(a[3]), "r"(b[0]), "r"(b[1]));
}
__device__ __forceinline__ void cp16(uint32_t s, const void* g, bool p) {
    asm volatile("cp.async.cg.shared.global [%0], [%1], 16, %2;"
                 :: "r"(s), "l"(g), "r"(p ? 16 : 0));
}

#define A_STRIDE 80u
#define B_STRIDE 272u
#define A_BYTES (128u * A_STRIDE)            // 10240
#define B_BYTES (32u * B_STRIDE)             // 8704
#define STAGE (2u * A_BYTES + 2u * B_BYTES)  // 37888
#define GEMM_SMEM (2 * STAGE)                // 75776 -> 2 CTAs/SM

// out[M,128] = (A1|A2)[M,K=256] @ W[K,128] + bias ; 3-term bf16 split.
// A1/A2 interleaved rows (hi @ +0, lo @ +128, stride RS).
// If out16a: gridDim.y==2 -> y==1 selects W+256 rows, bias+128, out16b.
__global__ __launch_bounds__(256, 2) void k_gemm_tc(
    const bf16* __restrict__ A1, const bf16* __restrict__ A2,
    const bf16* __restrict__ Wh, const bf16* __restrict__ Wl,
    const float* __restrict__ bias,
    bf16* __restrict__ outp,
    __half* __restrict__ out16a, __half* __restrict__ out16b,
    int M, int K)
{
    extern __shared__ char smdyn[];
    uint32_t base = (uint32_t)__cvta_generic_to_shared(smdyn);

    __half* o16 = out16a;
    if (out16a && blockIdx.y == 1) {
        Wh += 256 * D; Wl += 256 * D; bias += 128; o16 = out16b;
    }

    int tid = threadIdx.x;
    int wid = tid >> 5, lane = tid & 31;
    int warp_m = (wid >> 2) * 64;
    int warp_n = (wid & 3) * 32;
    int m0 = blockIdx.x * 128;
    int nch = K / 32;

    float c[4][4][4];
    #pragma unroll
    for (int i = 0; i < 4; i++)
        #pragma unroll
        for (int j = 0; j < 4; j++)
            #pragma unroll
            for (int q = 0; q < 4; q++) c[i][j][q] = 0.f;

    auto load_chunk = [&](int ch) {
        uint32_t st = base + (uint32_t)(ch & 1) * STAGE;
        int kb = ch * 32;
        const bf16* A = (kb < 128) ? A1 : A2;
        int ac = kb & 127;
        #pragma unroll
        for (int l = tid; l < 512; l += 256) {      // A: 128 rows x 4 segs
            int r = l >> 2, seg = l & 3;
            uint32_t so = (uint32_t)r * A_STRIDE + (uint32_t)seg * 16u;
            bool p = (m0 + r) < M;
            int rr = p ? (m0 + r) : 0;
            size_t go = (size_t)rr * RS + ac + seg * 8;
            cp16(st + so,           A + go, p);          // hi
            cp16(st + A_BYTES + so, A + go + 128, p);    // lo
        }
        #pragma unroll
        for (int l = tid; l < 512; l += 256) {      // B: 32 rows x 16 segs
            int r = l >> 4, seg = l & 15;
            uint32_t so = (uint32_t)r * B_STRIDE + (uint32_t)seg * 16u;
            size_t go = (size_t)(kb + r) * D + seg * 8;
            cp16(st + 2u * A_BYTES + so,           Wh + go, true);
            cp16(st + 2u * A_BYTES + B_BYTES + so, Wl + go, true);
        }
        asm volatile("cp.async.commit_group;" ::: "memory");
    };

    load_chunk(0);

    int lr = (lane & 7) + 8 * ((lane >> 3) & 1);
    int lc = 8 * (lane >> 4);

    for (int ch = 0; ch < nch; ch++) {
        asm volatile("cp.async.wait_group 0;" ::: "memory");
        __syncthreads();
        if (ch + 1 < nch) load_chunk(ch + 1);   // into stage freed last iter

        uint32_t st   = base + (uint32_t)(ch & 1) * STAGE;
        uint32_t ah_b = st;
        uint32_t al_b = st + A_BYTES;
        uint32_t bh_b = st + 2u * A_BYTES;
        uint32_t bl_b = bh_b + B_BYTES;

        #pragma unroll
        for (int ks = 0; ks < 2; ks++) {
            int k0 = ks * 16;
            uint32_t ah[4][4], al_[4][4];
            #pragma unroll
            for (int mi = 0; mi < 4; mi++) {
                uint32_t ro = (uint32_t)(warp_m + mi * 16 + lr) * A_STRIDE
                            + (uint32_t)(k0 + lc) * 2u;
                ldsm4(ah[mi][0], ah[mi][1], ah[mi][2], ah[mi][3], ah_b + ro);
                ldsm4(al_[mi][0], al_[mi][1], al_[mi][2], al_[mi][3], al_b + ro);
            }
            uint32_t bh[4][2], bl[4][2];
            #pragma unroll
            for (int njp = 0; njp < 2; njp++) {
                uint32_t ro = (uint32_t)(k0 + lr) * B_STRIDE
                            + (uint32_t)(warp_n + njp * 16 + lc) * 2u;
                uint32_t r0, r1, r2, r3;
                ldsm4t(r0, r1, r2, r3, bh_b + ro);
                bh[2 * njp][0] = r0;     bh[2 * njp][1] = r1;
                bh[2 * njp + 1][0] = r2; bh[2 * njp + 1][1] = r3;
                ldsm4t(r0, r1, r2, r3, bl_b + ro);
                bl[2 * njp][0] = r0;     bl[2 * njp][1] = r1;
                bl[2 * njp + 1][0] = r2; bl[2 * njp + 1][1] = r3;
            }
            #pragma unroll
            for (int mi = 0; mi < 4; mi++)
                #pragma unroll
                for (int nj = 0; nj < 4; nj++) {
                    mma_bf16(c[mi][nj], ah[mi], bh[nj]);
                    mma_bf16(c[mi][nj], ah[mi], bl[nj]);
                    mma_bf16(c[mi][nj], al_[mi], bh[nj]);
                }
        }
        if (ch + 1 < nch) __syncthreads();   // protect stage reuse vs slow warps
    }

    // epilogue
    #pragma unroll
    for (int mi = 0; mi < 4; mi++) {
        #pragma unroll
        for (int nj = 0; nj < 4; nj++) {
            int row0 = m0 + warp_m + mi * 16 + (lane >> 2);
            int col  = warp_n + nj * 8 + (lane & 3) * 2;
            float b0 = bias ? bias[col] : 0.f;
            float b1 = bias ? bias[col + 1] : 0.f;
            #pragma unroll
            for (int h = 0; h < 2; h++) {
                int row = row0 + 8 * h;
                if (row < M) {
                    float v0 = c[mi][nj][2 * h]     + b0;
                    float v1 = c[mi][nj][2 * h + 1] + b1;
                    if (o16) {
                        *(__half2*)&o16[(size_t)row * D + col] =
                            __floats2half2_rn(v0, v1);
                    } else {
                        bf16 h0, l0, h1, l1;
                        split_bf16(v0, h0, l0); split_bf16(v1, h1, l1);
                        *(bf162*)&outp[(size_t)row * RS + col] = __halves2bfloat162(h0, h1);
                        *(bf162*)&outp[(size_t)row * RS + 128 + col] = __halves2bfloat162(l0, l1);
                    }
                }
            }
        }
    }
}

// ---------------- edge scoring (fp16 projections) ---------------------------
__global__ void k_edge(const int* __restrict__ s1, const int* __restrict__ d1,
                       const int* __restrict__ s2, const int* __restrict__ d2,
                       const float* __restrict__ Wp2, const float* __restrict__ bp2,
                       float* __restrict__ out)
{
    int gw   = (blockIdx.x * blockDim.x + threadIdx.x) >> 5;
    int lane = threadIdx.x & 31;
    if (gw >= 2 * N_EDGES) return;
    int ss, dd;
    if (gw < N_EDGES) { ss = s1[gw]; dd = d1[gw]; }
    else              { ss = s2[gw - N_EDGES]; dd = d2[gw - N_EDGES]; }

    uint2 av = *(const uint2*)&g_pa16[(size_t)ss * D + lane * 4];
    uint2 bv = *(const uint2*)&g_pb16[(size_t)dd * D + lane * 4];
    float2 a0 = __half22float2(*(__half2*)&av.x);
    float2 a1 = __half22float2(*(__half2*)&av.y);
    float2 b0 = __half22float2(*(__half2*)&bv.x);
    float2 b1 = __half22float2(*(__half2*)&bv.y);
    float4 w = *(const float4*)&Wp2[lane * 4];

    float p = fmaxf(a0.x + b0.x, 0.f) * w.x
            + fmaxf(a0.y + b0.y, 0.f) * w.y
            + fmaxf(a1.x + b1.x, 0.f) * w.z
            + fmaxf(a1.y + b1.y, 0.f) * w.w;
    #pragma unroll
    for (int o = 16; o > 0; o >>= 1) p += __shfl_xor_sync(0xffffffffu, p, o);
    if (lane == 0) out[gw] = p + bp2[0];
}

// ---------------- launch ----------------------------------------------------
extern "C" void kernel_launch(void* const* d_in, const int* in_sizes, int n_in,
                              void* d_out, int out_size)
{
    const float* x    = (const float*)d_in[0];
    const int*   src  = (const int*)d_in[1];
    const int*   dst  = (const int*)d_in[2];
    const int*   nsrc = (const int*)d_in[3];
    const int*   ndst = (const int*)d_in[4];
    const float* Ws1 = (const float*)d_in[5],  *Wn1 = (const float*)d_in[6],  *b1 = (const float*)d_in[7];
    const float* Ws2 = (const float*)d_in[8],  *Wn2 = (const float*)d_in[9],  *b2 = (const float*)d_in[10];
    const float* Ws3 = (const float*)d_in[11], *Wn3 = (const float*)d_in[12], *b3 = (const float*)d_in[13];
    const float* Wp1 = (const float*)d_in[14], *bp1 = (const float*)d_in[15];
    const float* Wp2 = (const float*)d_in[16], *bp2 = (const float*)d_in[17];
    float* out = (float*)d_out;

    __half *p_pa16, *p_pb16;
    bf16 *p_x, *p_m, *p_h1, *p_h2, *p_wh, *p_wl;
    float* p_bc;
    cudaGetSymbolAddress((void**)&p_pa16, g_pa16);
    cudaGetSymbolAddress((void**)&p_pb16, g_pb16);
    cudaGetSymbolAddress((void**)&p_x, g_x);
    cudaGetSymbolAddress((void**)&p_m, g_m);
    cudaGetSymbolAddress((void**)&p_h1, g_h1);
    cudaGetSymbolAddress((void**)&p_h2, g_h2);
    cudaGetSymbolAddress((void**)&p_wh, g_wh);
    cudaGetSymbolAddress((void**)&p_wl, g_wl);
    cudaGetSymbolAddress((void**)&p_bc, g_bc);

    cudaFuncSetAttribute(k_gemm_tc, cudaFuncAttributeMaxDynamicSharedMemorySize,
                         GEMM_SMEM);

    // --- build CSR ---
    k_zero_cnt<<<(N_NODES + 255) / 256, 256>>>();
    k_hist<<<(N_EDGES + 255) / 256, 256>>>(dst);
    k_blockscan<<<NB_SCAN, 1024>>>();
    k_scan_bsum<<<1, 128>>>();
    k_addoff<<<(N_NODES + 255) / 256, 256>>>();
    k_place<<<(N_EDGES + 255) / 256, 256>>>(src, dst);

    // --- conversions + weight composition ---
    int n4 = N_NODES * D / 4;
    k_cvt4<<<(n4 + 255) / 256, 256>>>(x, p_x, n4);
    k_cvt_w<<<(512 * D + 255) / 256, 256>>>(Ws1, Wn1, Ws2, Wn2);
    k_compose<<<512, 128>>>(Ws3, Wn3, Wp1);
    k_bias_comp<<<2, 128>>>(b3, Wp1, bp1);

    const int aggBlocks  = (N_NODES * 32 + 255) / 256;
    const int gemmBlocks = (N_NODES + 127) / 128;

    // --- layer 1 ---
    k_agg<<<aggBlocks, 256>>>(p_x);
    k_gemm_tc<<<gemmBlocks, 256, GEMM_SMEM>>>(p_x, p_m, p_wh, p_wl, b1,
                                              p_h1, nullptr, nullptr, N_NODES, 256);
    // --- layer 2 ---
    k_agg<<<aggBlocks, 256>>>(p_h1);
    k_gemm_tc<<<gemmBlocks, 256, GEMM_SMEM>>>(p_h1, p_m, p_wh + 256 * D, p_wl + 256 * D, b2,
                                              p_h2, nullptr, nullptr, N_NODES, 256);
    // --- layer 3 + predictor (fused via composed weights; gridDim.y=2) ---
    k_agg<<<aggBlocks, 256>>>(p_h2);
    k_gemm_tc<<<dim3(gemmBlocks, 2), 256, GEMM_SMEM>>>(
                                              p_h2, p_m, p_wh + 512 * D, p_wl + 512 * D, p_bc,
                                              nullptr, p_pa16, p_pb16, N_NODES, 256);

    // --- edge scores ---
    k_edge<<<(2 * N_EDGES * 32 + 255) / 256, 256>>>(src, dst, nsrc, ndst, Wp2, bp2, out);
}

// round 9
// speedup vs baseline: 1.2395x; 1.1269x over previous
#include <cuda_runtime.h>
#include <cuda_bf16.h>
#include <cuda_fp16.h>
#include <cstdint>

#define N_NODES 100000
#define N_EDGES 640000
#define D 128
#define RS 256                               // interleaved row stride (hi|lo)
#define NB_SCAN ((N_NODES + 1023) / 1024)    // 98

typedef __nv_bfloat16 bf16;
typedef __nv_bfloat162 bf162;

// ---------------- scratch (device globals: no allocation allowed) ----------
__device__ __align__(16) __half g_pa16[N_NODES * D];
__device__ __align__(16) __half g_pb16[N_NODES * D];
// interleaved node tensors: row = [128 hi | 128 lo] bf16
__device__ __align__(16) bf16 g_x[N_NODES * RS];
__device__ __align__(16) bf16 g_m[N_NODES * RS];
__device__ __align__(16) bf16 g_h1[N_NODES * RS];
__device__ __align__(16) bf16 g_h2[N_NODES * RS];
// packed weights [K][N]: rows [Ws1|Wn1|Ws2|Wn2 | comp_pa(256) | comp_pb(256)]
__device__ __align__(16) bf16 g_wh[1024 * D];
__device__ __align__(16) bf16 g_wl[1024 * D];
__device__ float g_bc[2 * D];                // composed predictor biases
// CSR
__device__ int g_cnt[N_NODES];
__device__ int g_rowptr[N_NODES + 1];
__device__ int g_csr[N_EDGES];
__device__ int g_bsum[NB_SCAN];
__device__ int g_boff[NB_SCAN];

// ---------------- CSR construction ----------------------------------------
__global__ void k_zero_cnt() {
    int i = blockIdx.x * blockDim.x + threadIdx.x;
    if (i < N_NODES) g_cnt[i] = 0;
}
__global__ void k_hist(const int* __restrict__ dst) {
    int e = blockIdx.x * blockDim.x + threadIdx.x;
    if (e < N_EDGES) atomicAdd(&g_cnt[dst[e]], 1);
}
__global__ void k_blockscan() {
    __shared__ int sh[1024];
    int tid = threadIdx.x;
    int i = blockIdx.x * 1024 + tid;
    int v = (i < N_NODES) ? g_cnt[i] : 0;
    sh[tid] = v;
    __syncthreads();
    for (int o = 1; o < 1024; o <<= 1) {
        int t = (tid >= o) ? sh[tid - o] : 0;
        __syncthreads();
        sh[tid] += t;
        __syncthreads();
    }
    if (i < N_NODES) g_rowptr[i] = sh[tid] - v;
    if (tid == 1023) g_bsum[blockIdx.x] = sh[1023];
}
__global__ void k_scan_bsum() {
    __shared__ int sh[128];
    int t = threadIdx.x;
    int v = (t < NB_SCAN) ? g_bsum[t] : 0;
    sh[t] = v;
    __syncthreads();
    for (int o = 1; o < 128; o <<= 1) {
        int u = (t >= o) ? sh[t - o] : 0;
        __syncthreads();
        sh[t] += u;
        __syncthreads();
    }
    if (t < NB_SCAN) g_boff[t] = sh[t] - v;
    if (t == NB_SCAN - 1) g_rowptr[N_NODES] = sh[t];
}
__global__ void k_addoff() {
    int i = blockIdx.x * blockDim.x + threadIdx.x;
    if (i < N_NODES) {
        g_rowptr[i] += g_boff[i >> 10];
        g_cnt[i] = 0;
    }
}
__global__ void k_place(const int* __restrict__ src, const int* __restrict__ dst) {
    int e = blockIdx.x * blockDim.x + threadIdx.x;
    if (e < N_EDGES) {
        int d = dst[e];
        int slot = g_rowptr[d] + atomicAdd(&g_cnt[d], 1);
        g_csr[slot] = src[e];
    }
}

// ---------------- conversions ----------------------------------------------
__device__ __forceinline__ void split_bf16(float v, bf16& h, bf16& l) {
    h = __float2bfloat16_rn(v);
    l = __float2bfloat16_rn(v - __bfloat162float(h));
}

// x fp32 -> interleaved hi/lo rows
__global__ void k_cvt4(const float* __restrict__ in, bf16* __restrict__ o, int n4) {
    int i = blockIdx.x * blockDim.x + threadIdx.x;
    if (i >= n4) return;
    float4 v = ((const float4*)in)[i];
    bf16 hx, hy, hz, hw, lx, ly, lz, lw;
    split_bf16(v.x, hx, lx); split_bf16(v.y, hy, ly);
    split_bf16(v.z, hz, lz); split_bf16(v.w, hw, lw);
    int row = i >> 5, d4 = (i & 31) * 4;
    bf162* ph = (bf162*)&o[row * RS + d4];
    bf162* pl = (bf162*)&o[row * RS + 128 + d4];
    ph[0] = __halves2bfloat162(hx, hy); ph[1] = __halves2bfloat162(hz, hw);
    pl[0] = __halves2bfloat162(lx, ly); pl[1] = __halves2bfloat162(lz, lw);
}

// layer 1/2 weights -> rows 0..511
__global__ void k_cvt_w(const float* Ws1, const float* Wn1,
                        const float* Ws2, const float* Wn2) {
    int i = blockIdx.x * blockDim.x + threadIdx.x;   // 0 .. 512*128-1
    if (i >= 512 * D) return;
    int row = i >> 7, col = i & 127;
    const float* s; int lr;
    if      (row < 128)  { s = Ws1; lr = row; }
    else if (row < 256)  { s = Wn1; lr = row - 128; }
    else if (row < 384)  { s = Ws2; lr = row - 256; }
    else                 { s = Wn2; lr = row - 384; }
    float v = s[lr * D + col];
    bf16 h, l; split_bf16(v, h, l);
    g_wh[i] = h; g_wl[i] = l;
}

// composed predictor weights: rows 512..1023
__global__ void k_compose(const float* __restrict__ Ws3, const float* __restrict__ Wn3,
                          const float* __restrict__ Wp1) {
    int p = blockIdx.x >> 7, i = blockIdx.x & 127;
    const float* X = (p & 1) ? Wn3 : Ws3;
    const float* Y = Wp1 + ((p >> 1) ? 128 * D : 0);
    __shared__ float xr[128];
    int n = threadIdx.x;
    xr[n] = X[i * D + n];
    __syncthreads();
    float s = 0.f;
    #pragma unroll 8
    for (int k = 0; k < 128; k++) s += xr[k] * Y[k * D + n];
    int dst = ((p < 2) ? 512 : 768) + (p & 1) * 128 + i;
    bf16 h, l; split_bf16(s, h, l);
    g_wh[dst * D + n] = h; g_wl[dst * D + n] = l;
}
__global__ void k_bias_comp(const float* __restrict__ b3, const float* __restrict__ Wp1,
                            const float* __restrict__ bp1) {
    int n = threadIdx.x, half = blockIdx.x;
    float s = (half == 0) ? bp1[n] : 0.f;
    for (int j = 0; j < 128; j++) s += b3[j] * Wp1[(half * 128 + j) * D + n];
    g_bc[half * D + n] = s;
}

// ---------------- mean aggregation: interleaved rows, 1 LDG.128/edge/lane --
__global__ void k_agg(const bf16* __restrict__ xin) {
    int gw   = (blockIdx.x * blockDim.x + threadIdx.x) >> 5;
    int lane = threadIdx.x & 31;
    if (gw >= N_NODES) return;
    int beg = g_rowptr[gw], end = g_rowptr[gw + 1];
    float acc[8];
    #pragma unroll
    for (int j = 0; j < 8; j++) acc[j] = 0.f;
    for (int e = beg; e < end; e++) {
        const uint4 v = *(const uint4*)&xin[(size_t)g_csr[e] * RS + lane * 8];
        float2 f0 = __bfloat1622float2(*(bf162*)&v.x);
        float2 f1 = __bfloat1622float2(*(bf162*)&v.y);
        float2 f2 = __bfloat1622float2(*(bf162*)&v.z);
        float2 f3 = __bfloat1622float2(*(bf162*)&v.w);
        acc[0] += f0.x; acc[1] += f0.y; acc[2] += f1.x; acc[3] += f1.y;
        acc[4] += f2.x; acc[5] += f2.y; acc[6] += f3.x; acc[7] += f3.y;
    }
    #pragma unroll
    for (int j = 0; j < 8; j++)
        acc[j] += __shfl_xor_sync(0xffffffffu, acc[j], 16);
    int deg = end - beg;
    float inv = 1.0f / (float)(deg > 1 ? deg : 1);
    bf16 hs[8], ls[8];
    #pragma unroll
    for (int j = 0; j < 8; j++) {
        float v = acc[j] * inv;
        split_bf16(v, hs[j], ls[j]);
    }
    uint4 outv;
    bf162* op = (bf162*)&outv;
    if (lane < 16) {
        op[0] = __halves2bfloat162(hs[0], hs[1]); op[1] = __halves2bfloat162(hs[2], hs[3]);
        op[2] = __halves2bfloat162(hs[4], hs[5]); op[3] = __halves2bfloat162(hs[6], hs[7]);
        *(uint4*)&g_m[(size_t)gw * RS + lane * 8] = outv;
    } else {
        op[0] = __halves2bfloat162(ls[0], ls[1]); op[1] = __halves2bfloat162(ls[2], ls[3]);
        op[2] = __halves2bfloat162(ls[4], ls[5]); op[3] = __halves2bfloat162(ls[6], ls[7]);
        *(uint4*)&g_m[(size_t)gw * RS + 128 + (lane - 16) * 8] = outv;
    }
}

// ---------------- tensor-core GEMM (256 thr, 3-stage, 2 CTA/SM) ------------
__device__ __forceinline__ void ldsm4(uint32_t& r0, uint32_t& r1, uint32_t& r2,
                                      uint32_t& r3, uint32_t addr) {
    asm volatile("ldmatrix.sync.aligned.m8n8.x4.shared.b16 {%0,%1,%2,%3}, [%4];"
                 : "=r"(r0), "=r"(r1), "=r"(r2), "=r"(r3) : "r"(addr));
}
__device__ __forceinline__ void ldsm4t(uint32_t& r0, uint32_t& r1, uint32_t& r2,
                                       uint32_t& r3, uint32_t addr) {
    asm volatile("ldmatrix.sync.aligned.m8n8.x4.trans.shared.b16 {%0,%1,%2,%3}, [%4];"
                 : "=r"(r0), "=r"(r1), "=r"(r2), "=r"(r3) : "r"(addr));
}
__device__ __forceinline__ void mma_bf16(float* c, const uint32_t* a, const uint32_t* b) {
    asm volatile(
        "mma.sync.aligned.m16n8k16.row.col.f32.bf16.bf16.f32 "
        "{%0,%1,%2,%3},{%4,%5,%6,%7},{%8,%9},{%0,%1,%2,%3};"
        : "+f"(c[0]), "+f"(c[1]), "+f"(c[2]), "+f"(c[3])
        : "r"(a[0]), "r"(a[1]), "r"(a[2]), "r"(a[3]), "r"(b[0]), "r"(b[1]));
}
__device__ __forceinline__ void cp16(uint32_t s, const void* g, bool p) {
    asm volatile("cp.async.cg.shared.global [%0], [%1], 16, %2;"
                 :: "r"(s), "l"(g), "r"(p ? 16 : 0));
}

#define A_STRIDE 80u
#define B_STRIDE 272u
#define A_BYTES (128u * A_STRIDE)            // 10240
#define B_BYTES (32u * B_STRIDE)             // 8704
#define STAGE (2u * A_BYTES + 2u * B_BYTES)  // 37888
#define GEMM_SMEM (3 * STAGE)                // 113664 -> still 2 CTAs/SM

// out[M,128] = (A1|A2)[M,K=256] @ W[K,128] + bias ; 3-term bf16 split.
// A1/A2 interleaved rows (hi @ +0, lo @ +128, stride RS).
// If out16a: gridDim.y==2 -> y==1 selects W+256 rows, bias+128, out16b.
__global__ __launch_bounds__(256, 2) void k_gemm_tc(
    const bf16* __restrict__ A1, const bf16* __restrict__ A2,
    const bf16* __restrict__ Wh, const bf16* __restrict__ Wl,
    const float* __restrict__ bias,
    bf16* __restrict__ outp,
    __half* __restrict__ out16a, __half* __restrict__ out16b,
    int M, int K)
{
    extern __shared__ char smdyn[];
    uint32_t base = (uint32_t)__cvta_generic_to_shared(smdyn);

    __half* o16 = out16a;
    if (out16a && blockIdx.y == 1) {
        Wh += 256 * D; Wl += 256 * D; bias += 128; o16 = out16b;
    }

    int tid = threadIdx.x;
    int wid = tid >> 5, lane = tid & 31;
    int warp_m = (wid >> 2) * 64;
    int warp_n = (wid & 3) * 32;
    int m0 = blockIdx.x * 128;
    int nch = K / 32;

    float c[4][4][4];
    #pragma unroll
    for (int i = 0; i < 4; i++)
        #pragma unroll
        for (int j = 0; j < 4; j++)
            #pragma unroll
            for (int q = 0; q < 4; q++) c[i][j][q] = 0.f;

    auto load_chunk = [&](int ch) {
        uint32_t st = base + (uint32_t)(ch % 3) * STAGE;
        int kb = ch * 32;
        const bf16* A = (kb < 128) ? A1 : A2;
        int ac = kb & 127;
        #pragma unroll
        for (int l = tid; l < 512; l += 256) {      // A: 128 rows x 4 segs
            int r = l >> 2, seg = l & 3;
            uint32_t so = (uint32_t)r * A_STRIDE + (uint32_t)seg * 16u;
            bool p = (m0 + r) < M;
            int rr = p ? (m0 + r) : 0;
            size_t go = (size_t)rr * RS + ac + seg * 8;
            cp16(st + so,           A + go, p);          // hi
            cp16(st + A_BYTES + so, A + go + 128, p);    // lo
        }
        #pragma unroll
        for (int l = tid; l < 512; l += 256) {      // B: 32 rows x 16 segs
            int r = l >> 4, seg = l & 15;
            uint32_t so = (uint32_t)r * B_STRIDE + (uint32_t)seg * 16u;
            size_t go = (size_t)(kb + r) * D + seg * 8;
            cp16(st + 2u * A_BYTES + so,           Wh + go, true);
            cp16(st + 2u * A_BYTES + B_BYTES + so, Wl + go, true);
        }
        asm volatile("cp.async.commit_group;" ::: "memory");
    };

    load_chunk(0);
    load_chunk(1);

    int lr = (lane & 7) + 8 * ((lane >> 3) & 1);
    int lc = 8 * (lane >> 4);

    for (int ch = 0; ch < nch; ch++) {
        if (ch + 1 < nch) {
            asm volatile("cp.async.wait_group 1;" ::: "memory");
        } else {
            asm volatile("cp.async.wait_group 0;" ::: "memory");
        }
        __syncthreads();     // single barrier: orders stage reuse + visibility
        if (ch + 2 < nch) load_chunk(ch + 2);

        uint32_t st   = base + (uint32_t)(ch % 3) * STAGE;
        uint32_t ah_b = st;
        uint32_t al_b = st + A_BYTES;
        uint32_t bh_b = st + 2u * A_BYTES;
        uint32_t bl_b = bh_b + B_BYTES;

        #pragma unroll
        for (int ks = 0; ks < 2; ks++) {
            int k0 = ks * 16;
            uint32_t ah[4][4], al_[4][4];
            #pragma unroll
            for (int mi = 0; mi < 4; mi++) {
                uint32_t ro = (uint32_t)(warp_m + mi * 16 + lr) * A_STRIDE
                            + (uint32_t)(k0 + lc) * 2u;
                ldsm4(ah[mi][0], ah[mi][1], ah[mi][2], ah[mi][3], ah_b + ro);
                ldsm4(al_[mi][0], al_[mi][1], al_[mi][2], al_[mi][3], al_b + ro);
            }
            uint32_t bh[4][2], bl[4][2];
            #pragma unroll
            for (int njp = 0; njp < 2; njp++) {
                uint32_t ro = (uint32_t)(k0 + lr) * B_STRIDE
                            + (uint32_t)(warp_n + njp * 16 + lc) * 2u;
                uint32_t r0, r1, r2, r3;
                ldsm4t(r0, r1, r2, r3, bh_b + ro);
                bh[2 * njp][0] = r0;     bh[2 * njp][1] = r1;
                bh[2 * njp + 1][0] = r2; bh[2 * njp + 1][1] = r3;
                ldsm4t(r0, r1, r2, r3, bl_b + ro);
                bl[2 * njp][0] = r0;     bl[2 * njp][1] = r1;
                bl[2 * njp + 1][0] = r2; bl[2 * njp + 1][1] = r3;
            }
            #pragma unroll
            for (int mi = 0; mi < 4; mi++)
                #pragma unroll
                for (int nj = 0; nj < 4; nj++) {
                    mma_bf16(c[mi][nj], ah[mi], bh[nj]);
                    mma_bf16(c[mi][nj], ah[mi], bl[nj]);
                    mma_bf16(c[mi][nj], al_[mi], bh[nj]);
                }
        }
    }

    // epilogue
    #pragma unroll
    for (int mi = 0; mi < 4; mi++) {
        #pragma unroll
        for (int nj = 0; nj < 4; nj++) {
            int row0 = m0 + warp_m + mi * 16 + (lane >> 2);
            int col  = warp_n + nj * 8 + (lane & 3) * 2;
            float b0 = bias ? bias[col] : 0.f;
            float b1 = bias ? bias[col + 1] : 0.f;
            #pragma unroll
            for (int h = 0; h < 2; h++) {
                int row = row0 + 8 * h;
                if (row < M) {
                    float v0 = c[mi][nj][2 * h]     + b0;
                    float v1 = c[mi][nj][2 * h + 1] + b1;
                    if (o16) {
                        *(__half2*)&o16[(size_t)row * D + col] =
                            __floats2half2_rn(v0, v1);
                    } else {
                        bf16 h0, l0, h1, l1;
                        split_bf16(v0, h0, l0); split_bf16(v1, h1, l1);
                        *(bf162*)&outp[(size_t)row * RS + col] = __halves2bfloat162(h0, h1);
                        *(bf162*)&outp[(size_t)row * RS + 128 + col] = __halves2bfloat162(l0, l1);
                    }
                }
            }
        }
    }
}

// ---------------- edge scoring (fp16 projections, 16 lanes/edge) ------------
__global__ void k_edge(const int* __restrict__ s1, const int* __restrict__ d1,
                       const int* __restrict__ s2, const int* __restrict__ d2,
                       const float* __restrict__ Wp2, const float* __restrict__ bp2,
                       float* __restrict__ out)
{
    int g = blockIdx.x * blockDim.x + threadIdx.x;
    int e = g >> 4, lane16 = g & 15;
    if (e >= 2 * N_EDGES) return;
    int ss, dd;
    if (e < N_EDGES) { ss = s1[e]; dd = d1[e]; }
    else             { ss = s2[e - N_EDGES]; dd = d2[e - N_EDGES]; }

    uint4 av = *(const uint4*)&g_pa16[(size_t)ss * D + lane16 * 8];
    uint4 bv = *(const uint4*)&g_pb16[(size_t)dd * D + lane16 * 8];
    float4 w0 = *(const float4*)&Wp2[lane16 * 8];
    float4 w1 = *(const float4*)&Wp2[lane16 * 8 + 4];

    float2 a0 = __half22float2(*(__half2*)&av.x);
    float2 a1 = __half22float2(*(__half2*)&av.y);
    float2 a2 = __half22float2(*(__half2*)&av.z);
    float2 a3 = __half22float2(*(__half2*)&av.w);
    float2 b0 = __half22float2(*(__half2*)&bv.x);
    float2 b1 = __half22float2(*(__half2*)&bv.y);
    float2 b2 = __half22float2(*(__half2*)&bv.z);
    float2 b3 = __half22float2(*(__half2*)&bv.w);

    float p = fmaxf(a0.x + b0.x, 0.f) * w0.x
            + fmaxf(a0.y + b0.y, 0.f) * w0.y
            + fmaxf(a1.x + b1.x, 0.f) * w0.z
            + fmaxf(a1.y + b1.y, 0.f) * w0.w
            + fmaxf(a2.x + b2.x, 0.f) * w1.x
            + fmaxf(a2.y + b2.y, 0.f) * w1.y
            + fmaxf(a3.x + b3.x, 0.f) * w1.z
            + fmaxf(a3.y + b3.y, 0.f) * w1.w;
    #pragma unroll
    for (int o = 8; o > 0; o >>= 1) p += __shfl_xor_sync(0xffffffffu, p, o);
    if (lane16 == 0) out[e] = p + bp2[0];
}

// ---------------- launch ----------------------------------------------------
extern "C" void kernel_launch(void* const* d_in, const int* in_sizes, int n_in,
                              void* d_out, int out_size)
{
    const float* x    = (const float*)d_in[0];
    const int*   src  = (const int*)d_in[1];
    const int*   dst  = (const int*)d_in[2];
    const int*   nsrc = (const int*)d_in[3];
    const int*   ndst = (const int*)d_in[4];
    const float* Ws1 = (const float*)d_in[5],  *Wn1 = (const float*)d_in[6],  *b1 = (const float*)d_in[7];
    const float* Ws2 = (const float*)d_in[8],  *Wn2 = (const float*)d_in[9],  *b2 = (const float*)d_in[10];
    const float* Ws3 = (const float*)d_in[11], *Wn3 = (const float*)d_in[12], *b3 = (const float*)d_in[13];
    const float* Wp1 = (const float*)d_in[14], *bp1 = (const float*)d_in[15];
    const float* Wp2 = (const float*)d_in[16], *bp2 = (const float*)d_in[17];
    float* out = (float*)d_out;

    __half *p_pa16, *p_pb16;
    bf16 *p_x, *p_m, *p_h1, *p_h2, *p_wh, *p_wl;
    float* p_bc;
    cudaGetSymbolAddress((void**)&p_pa16, g_pa16);
    cudaGetSymbolAddress((void**)&p_pb16, g_pb16);
    cudaGetSymbolAddress((void**)&p_x, g_x);
    cudaGetSymbolAddress((void**)&p_m, g_m);
    cudaGetSymbolAddress((void**)&p_h1, g_h1);
    cudaGetSymbolAddress((void**)&p_h2, g_h2);
    cudaGetSymbolAddress((void**)&p_wh, g_wh);
    cudaGetSymbolAddress((void**)&p_wl, g_wl);
    cudaGetSymbolAddress((void**)&p_bc, g_bc);

    cudaFuncSetAttribute(k_gemm_tc, cudaFuncAttributeMaxDynamicSharedMemorySize,
                         GEMM_SMEM);

    // --- build CSR ---
    k_zero_cnt<<<(N_NODES + 255) / 256, 256>>>();
    k_hist<<<(N_EDGES + 255) / 256, 256>>>(dst);
    k_blockscan<<<NB_SCAN, 1024>>>();
    k_scan_bsum<<<1, 128>>>();
    k_addoff<<<(N_NODES + 255) / 256, 256>>>();
    k_place<<<(N_EDGES + 255) / 256, 256>>>(src, dst);

    // --- conversions + weight composition ---
    int n4 = N_NODES * D / 4;
    k_cvt4<<<(n4 + 255) / 256, 256>>>(x, p_x, n4);
    k_cvt_w<<<(512 * D + 255) / 256, 256>>>(Ws1, Wn1, Ws2, Wn2);
    k_compose<<<512, 128>>>(Ws3, Wn3, Wp1);
    k_bias_comp<<<2, 128>>>(b3, Wp1, bp1);

    const int aggBlocks  = (N_NODES * 32 + 255) / 256;
    const int gemmBlocks = (N_NODES + 127) / 128;

    // --- layer 1 ---
    k_agg<<<aggBlocks, 256>>>(p_x);
    k_gemm_tc<<<gemmBlocks, 256, GEMM_SMEM>>>(p_x, p_m, p_wh, p_wl, b1,
                                              p_h1, nullptr, nullptr, N_NODES, 256);
    // --- layer 2 ---
    k_agg<<<aggBlocks, 256>>>(p_h1);
    k_gemm_tc<<<gemmBlocks, 256, GEMM_SMEM>>>(p_h1, p_m, p_wh + 256 * D, p_wl + 256 * D, b2,
                                              p_h2, nullptr, nullptr, N_NODES, 256);
    // --- layer 3 + predictor (fused via composed weights; gridDim.y=2) ---
    k_agg<<<aggBlocks, 256>>>(p_h2);
    k_gemm_tc<<<dim3(gemmBlocks, 2), 256, GEMM_SMEM>>>(
                                              p_h2, p_m, p_wh + 512 * D, p_wl + 512 * D, p_bc,
                                              nullptr, p_pa16, p_pb16, N_NODES, 256);

    // --- edge scores ---
    k_edge<<<(2 * N_EDGES * 16 + 255) / 256, 256>>>(src, dst, nsrc, ndst, Wp2, bp2, out);
}

// round 10
// speedup vs baseline: 1.6057x; 1.2954x over previous
#include <cuda_runtime.h>
#include <cuda_bf16.h>
#include <cuda_fp16.h>
#include <cstdint>

#define N_NODES 100000
#define N_EDGES 640000
#define D 128
#define NB_SCAN ((N_NODES + 1023) / 1024)    // 98

// ---------------- scratch (device globals: no allocation allowed) ----------
__device__ __align__(16) __half g_pa16[N_NODES * D];
__device__ __align__(16) __half g_pb16[N_NODES * D];
// node tensors: fp16 [N][128]
__device__ __align__(16) __half g_x[N_NODES * D];
__device__ __align__(16) __half g_m[N_NODES * D];
__device__ __align__(16) __half g_h1[N_NODES * D];
__device__ __align__(16) __half g_h2[N_NODES * D];
// packed weights [K][N] fp16 hi/lo:
// rows [Ws1|Wn1 (0-255) | Ws2|Wn2 (256-511) | comp_pa (512-767) | comp_pb (768-1023)]
__device__ __align__(16) __half g_wh[1024 * D];
__device__ __align__(16) __half g_wl[1024 * D];
__device__ float g_bc[2 * D];                // composed predictor biases
// CSR
__device__ int g_cnt[N_NODES];
__device__ int g_rowptr[N_NODES + 1];
__device__ int g_csr[N_EDGES];
__device__ int g_bsum[NB_SCAN];
__device__ int g_boff[NB_SCAN];

// ---------------- CSR construction ----------------------------------------
__global__ void k_zero_cnt() {
    int i = blockIdx.x * blockDim.x + threadIdx.x;
    if (i < N_NODES) g_cnt[i] = 0;
}
__global__ void k_hist(const int* __restrict__ dst) {
    int e = blockIdx.x * blockDim.x + threadIdx.x;
    if (e < N_EDGES) atomicAdd(&g_cnt[dst[e]], 1);
}
__global__ void k_blockscan() {
    __shared__ int sh[1024];
    int tid = threadIdx.x;
    int i = blockIdx.x * 1024 + tid;
    int v = (i < N_NODES) ? g_cnt[i] : 0;
    sh[tid] = v;
    __syncthreads();
    for (int o = 1; o < 1024; o <<= 1) {
        int t = (tid >= o) ? sh[tid - o] : 0;
        __syncthreads();
        sh[tid] += t;
        __syncthreads();
    }
    if (i < N_NODES) g_rowptr[i] = sh[tid] - v;
    if (tid == 1023) g_bsum[blockIdx.x] = sh[1023];
}
__global__ void k_scan_bsum() {
    __shared__ int sh[128];
    int t = threadIdx.x;
    int v = (t < NB_SCAN) ? g_bsum[t] : 0;
    sh[t] = v;
    __syncthreads();
    for (int o = 1; o < 128; o <<= 1) {
        int u = (t >= o) ? sh[t - o] : 0;
        __syncthreads();
        sh[t] += u;
        __syncthreads();
    }
    if (t < NB_SCAN) g_boff[t] = sh[t] - v;
    if (t == NB_SCAN - 1) g_rowptr[N_NODES] = sh[t];
}
__global__ void k_addoff() {
    int i = blockIdx.x * blockDim.x + threadIdx.x;
    if (i < N_NODES) {
        g_rowptr[i] += g_boff[i >> 10];
        g_cnt[i] = 0;
    }
}
__global__ void k_place(const int* __restrict__ src, const int* __restrict__ dst) {
    int e = blockIdx.x * blockDim.x + threadIdx.x;
    if (e < N_EDGES) {
        int d = dst[e];
        int slot = g_rowptr[d] + atomicAdd(&g_cnt[d], 1);
        g_csr[slot] = src[e];
    }
}

// ---------------- conversions ----------------------------------------------
__device__ __forceinline__ void split_fp16(float v, __half& h, __half& l) {
    h = __float2half_rn(v);
    l = __float2half_rn(v - __half2float(h));
}

// x fp32 -> fp16 rows
__global__ void k_cvt4(const float* __restrict__ in, __half* __restrict__ o, int n4) {
    int i = blockIdx.x * blockDim.x + threadIdx.x;
    if (i >= n4) return;
    float4 v = ((const float4*)in)[i];
    __half2 h0 = __floats2half2_rn(v.x, v.y);
    __half2 h1 = __floats2half2_rn(v.z, v.w);
    __half2* p = (__half2*)&o[i * 4];
    p[0] = h0; p[1] = h1;
}

// layer 1/2 weights -> rows 0..511, fp16 hi/lo split
__global__ void k_cvt_w(const float* Ws1, const float* Wn1,
                        const float* Ws2, const float* Wn2) {
    int i = blockIdx.x * blockDim.x + threadIdx.x;   // 0 .. 512*128-1
    if (i >= 512 * D) return;
    int row = i >> 7, col = i & 127;
    const float* s; int lr;
    if      (row < 128)  { s = Ws1; lr = row; }
    else if (row < 256)  { s = Wn1; lr = row - 128; }
    else if (row < 384)  { s = Ws2; lr = row - 256; }
    else                 { s = Wn2; lr = row - 384; }
    float v = s[lr * D + col];
    __half h, l; split_fp16(v, h, l);
    g_wh[i] = h; g_wl[i] = l;
}

// composed predictor weights: rows 512..1023 (fp32 compose, fp16 split)
__global__ void k_compose(const float* __restrict__ Ws3, const float* __restrict__ Wn3,
                          const float* __restrict__ Wp1) {
    int p = blockIdx.x >> 7, i = blockIdx.x & 127;
    const float* X = (p & 1) ? Wn3 : Ws3;
    const float* Y = Wp1 + ((p >> 1) ? 128 * D : 0);
    __shared__ float xr[128];
    int n = threadIdx.x;
    xr[n] = X[i * D + n];
    __syncthreads();
    float s = 0.f;
    #pragma unroll 8
    for (int k = 0; k < 128; k++) s += xr[k] * Y[k * D + n];
    int dst = ((p < 2) ? 512 : 768) + (p & 1) * 128 + i;
    __half h, l; split_fp16(s, h, l);
    g_wh[dst * D + n] = h; g_wl[dst * D + n] = l;
}
__global__ void k_bias_comp(const float* __restrict__ b3, const float* __restrict__ Wp1,
                            const float* __restrict__ bp1) {
    int n = threadIdx.x, half = blockIdx.x;
    float s = (half == 0) ? bp1[n] : 0.f;
    for (int j = 0; j < 128; j++) s += b3[j] * Wp1[(half * 128 + j) * D + n];
    g_bc[half * D + n] = s;
}

// ---------------- mean aggregation: fp16 rows, 8 B/lane/edge ---------------
__global__ void k_agg(const __half* __restrict__ xin) {
    int gw   = (blockIdx.x * blockDim.x + threadIdx.x) >> 5;
    int lane = threadIdx.x & 31;
    if (gw >= N_NODES) return;
    int beg = g_rowptr[gw], end = g_rowptr[gw + 1];
    float acc0 = 0.f, acc1 = 0.f, acc2 = 0.f, acc3 = 0.f;
    for (int e = beg; e < end; e++) {
        const uint2 v = *(const uint2*)&xin[(size_t)g_csr[e] * D + lane * 4];
        float2 f0 = __half22float2(*(__half2*)&v.x);
        float2 f1 = __half22float2(*(__half2*)&v.y);
        acc0 += f0.x; acc1 += f0.y; acc2 += f1.x; acc3 += f1.y;
    }
    int deg = end - beg;
    float inv = 1.0f / (float)(deg > 1 ? deg : 1);
    uint2 outv;
    *(__half2*)&outv.x = __floats2half2_rn(acc0 * inv, acc1 * inv);
    *(__half2*)&outv.y = __floats2half2_rn(acc2 * inv, acc3 * inv);
    *(uint2*)&g_m[(size_t)gw * D + lane * 4] = outv;
}

// ---------------- tensor-core GEMM (fp16, 2-term, 3-stage, 2 CTA/SM) -------
__device__ __forceinline__ void ldsm4(uint32_t& r0, uint32_t& r1, uint32_t& r2,
                                      uint32_t& r3, uint32_t addr) {
    asm volatile("ldmatrix.sync.aligned.m8n8.x4.shared.b16 {%0,%1,%2,%3}, [%4];"
                 : "=r"(r0), "=r"(r1), "=r"(r2), "=r"(r3) : "r"(addr));
}
__device__ __forceinline__ void ldsm4t(uint32_t& r0, uint32_t& r1, uint32_t& r2,
                                       uint32_t& r3, uint32_t addr) {
    asm volatile("ldmatrix.sync.aligned.m8n8.x4.trans.shared.b16 {%0,%1,%2,%3}, [%4];"
                 : "=r"(r0), "=r"(r1), "=r"(r2), "=r"(r3) : "r"(addr));
}
__device__ __forceinline__ void mma_fp16(float* c, const uint32_t* a, const uint32_t* b) {
    asm volatile(
        "mma.sync.aligned.m16n8k16.row.col.f32.f16.f16.f32 "
        "{%0,%1,%2,%3},{%4,%5,%6,%7},{%8,%9},{%0,%1,%2,%3};"
        : "+f"(c[0]), "+f"(c[1]), "+f"(c[2]), "+f"(c[3])
        : "r"(a[0]), "r"(a[1]), "r"(a[2]), "r"(a[3]), "r"(b[0]), "r"(b[1]));
}
__device__ __forceinline__ void cp16(uint32_t s, const void* g, bool p) {
    asm volatile("cp.async.cg.shared.global [%0], [%1], 16, %2;"
                 :: "r"(s), "l"(g), "r"(p ? 16 : 0));
}

#define A_STRIDE 80u
#define B_STRIDE 272u
#define A_BYTES (128u * A_STRIDE)            // 10240
#define B_BYTES (32u * B_STRIDE)             // 8704
#define STAGE (A_BYTES + 2u * B_BYTES)       // 27648
#define GEMM_SMEM (3 * STAGE)                // 82944 -> 2 CTAs/SM

// out[M,128] = (A1|A2)[M,K=256] @ W[K,128] + bias ; fp16 A, fp16 hi/lo W.
// If pred (gridDim.y==2): y==1 selects W+256 rows, bias+128, out=outB.
__global__ __launch_bounds__(256, 2) void k_gemm_tc(
    const __half* __restrict__ A1, const __half* __restrict__ A2,
    const __half* __restrict__ Wh, const __half* __restrict__ Wl,
    const float* __restrict__ bias,
    __half* __restrict__ outA, __half* __restrict__ outB,
    int M, int K)
{
    extern __shared__ char smdyn[];
    uint32_t base = (uint32_t)__cvta_generic_to_shared(smdyn);

    __half* outp = outA;
    if (outB && blockIdx.y == 1) {
        Wh += 256 * D; Wl += 256 * D; bias += 128; outp = outB;
    }

    int tid = threadIdx.x;
    int wid = tid >> 5, lane = tid & 31;
    int warp_m = (wid >> 2) * 64;
    int warp_n = (wid & 3) * 32;
    int m0 = blockIdx.x * 128;
    int nch = K / 32;

    float c[4][4][4];
    #pragma unroll
    for (int i = 0; i < 4; i++)
        #pragma unroll
        for (int j = 0; j < 4; j++)
            #pragma unroll
            for (int q = 0; q < 4; q++) c[i][j][q] = 0.f;

    auto load_chunk = [&](int ch) {
        uint32_t st = base + (uint32_t)(ch % 3) * STAGE;
        int kb = ch * 32;
        const __half* A = (kb < 128) ? A1 : A2;
        int ac = kb & 127;
        #pragma unroll
        for (int l = tid; l < 512; l += 256) {      // A: 128 rows x 4 segs(16B)
            int r = l >> 2, seg = l & 3;
            uint32_t so = (uint32_t)r * A_STRIDE + (uint32_t)seg * 16u;
            bool p = (m0 + r) < M;
            int rr = p ? (m0 + r) : 0;
            cp16(st + so, A + (size_t)rr * D + ac + seg * 8, p);
        }
        #pragma unroll
        for (int l = tid; l < 512; l += 256) {      // B: 32 rows x 16 segs
            int r = l >> 4, seg = l & 15;
            uint32_t so = (uint32_t)r * B_STRIDE + (uint32_t)seg * 16u;
            size_t go = (size_t)(kb + r) * D + seg * 8;
            cp16(st + A_BYTES + so,           Wh + go, true);
            cp16(st + A_BYTES + B_BYTES + so, Wl + go, true);
        }
        asm volatile("cp.async.commit_group;" ::: "memory");
    };

    load_chunk(0);
    load_chunk(1);

    int lr = (lane & 7) + 8 * ((lane >> 3) & 1);
    int lc = 8 * (lane >> 4);

    for (int ch = 0; ch < nch; ch++) {
        if (ch + 1 < nch) {
            asm volatile("cp.async.wait_group 1;" ::: "memory");
        } else {
            asm volatile("cp.async.wait_group 0;" ::: "memory");
        }
        __syncthreads();     // single barrier: orders stage reuse + visibility
        if (ch + 2 < nch) load_chunk(ch + 2);

        uint32_t st   = base + (uint32_t)(ch % 3) * STAGE;
        uint32_t a_b  = st;
        uint32_t bh_b = st + A_BYTES;
        uint32_t bl_b = bh_b + B_BYTES;

        #pragma unroll
        for (int ks = 0; ks < 2; ks++) {
            int k0 = ks * 16;
            uint32_t a[4][4];
            #pragma unroll
            for (int mi = 0; mi < 4; mi++) {
                uint32_t ro = (uint32_t)(warp_m + mi * 16 + lr) * A_STRIDE
                            + (uint32_t)(k0 + lc) * 2u;
                ldsm4(a[mi][0], a[mi][1], a[mi][2], a[mi][3], a_b + ro);
            }
            uint32_t bh[4][2], bl[4][2];
            #pragma unroll
            for (int njp = 0; njp < 2; njp++) {
                uint32_t ro = (uint32_t)(k0 + lr) * B_STRIDE
                            + (uint32_t)(warp_n + njp * 16 + lc) * 2u;
                uint32_t r0, r1, r2, r3;
                ldsm4t(r0, r1, r2, r3, bh_b + ro);
                bh[2 * njp][0] = r0;     bh[2 * njp][1] = r1;
                bh[2 * njp + 1][0] = r2; bh[2 * njp + 1][1] = r3;
                ldsm4t(r0, r1, r2, r3, bl_b + ro);
                bl[2 * njp][0] = r0;     bl[2 * njp][1] = r1;
                bl[2 * njp + 1][0] = r2; bl[2 * njp + 1][1] = r3;
            }
            #pragma unroll
            for (int mi = 0; mi < 4; mi++)
                #pragma unroll
                for (int nj = 0; nj < 4; nj++) {
                    mma_fp16(c[mi][nj], a[mi], bh[nj]);
                    mma_fp16(c[mi][nj], a[mi], bl[nj]);
                }
        }
    }

    // epilogue: fp16 output
    #pragma unroll
    for (int mi = 0; mi < 4; mi++) {
        #pragma unroll
        for (int nj = 0; nj < 4; nj++) {
            int row0 = m0 + warp_m + mi * 16 + (lane >> 2);
            int col  = warp_n + nj * 8 + (lane & 3) * 2;
            float b0 = bias ? bias[col] : 0.f;
            float b1 = bias ? bias[col + 1] : 0.f;
            #pragma unroll
            for (int h = 0; h < 2; h++) {
                int row = row0 + 8 * h;
                if (row < M) {
                    float v0 = c[mi][nj][2 * h]     + b0;
                    float v1 = c[mi][nj][2 * h + 1] + b1;
                    *(__half2*)&outp[(size_t)row * D + col] =
                        __floats2half2_rn(v0, v1);
                }
            }
        }
    }
}

// ---------------- edge scoring (fp16 projections, 16 lanes/edge) ------------
__global__ void k_edge(const int* __restrict__ s1, const int* __restrict__ d1,
                       const int* __restrict__ s2, const int* __restrict__ d2,
                       const float* __restrict__ Wp2, const float* __restrict__ bp2,
                       float* __restrict__ out)
{
    int g = blockIdx.x * blockDim.x + threadIdx.x;
    int e = g >> 4, lane16 = g & 15;
    if (e >= 2 * N_EDGES) return;
    int ss, dd;
    if (e < N_EDGES) { ss = s1[e]; dd = d1[e]; }
    else             { ss = s2[e - N_EDGES]; dd = d2[e - N_EDGES]; }

    uint4 av = *(const uint4*)&g_pa16[(size_t)ss * D + lane16 * 8];
    uint4 bv = *(const uint4*)&g_pb16[(size_t)dd * D + lane16 * 8];
    float4 w0 = *(const float4*)&Wp2[lane16 * 8];
    float4 w1 = *(const float4*)&Wp2[lane16 * 8 + 4];

    float2 a0 = __half22float2(*(__half2*)&av.x);
    float2 a1 = __half22float2(*(__half2*)&av.y);
    float2 a2 = __half22float2(*(__half2*)&av.z);
    float2 a3 = __half22float2(*(__half2*)&av.w);
    float2 b0 = __half22float2(*(__half2*)&bv.x);
    float2 b1 = __half22float2(*(__half2*)&bv.y);
    float2 b2 = __half22float2(*(__half2*)&bv.z);
    float2 b3 = __half22float2(*(__half2*)&bv.w);

    float p = fmaxf(a0.x + b0.x, 0.f) * w0.x
            + fmaxf(a0.y + b0.y, 0.f) * w0.y
            + fmaxf(a1.x + b1.x, 0.f) * w0.z
            + fmaxf(a1.y + b1.y, 0.f) * w0.w
            + fmaxf(a2.x + b2.x, 0.f) * w1.x
            + fmaxf(a2.y + b2.y, 0.f) * w1.y
            + fmaxf(a3.x + b3.x, 0.f) * w1.z
            + fmaxf(a3.y + b3.y, 0.f) * w1.w;
    #pragma unroll
    for (int o = 8; o > 0; o >>= 1) p += __shfl_xor_sync(0xffffffffu, p, o);
    if (lane16 == 0) out[e] = p + bp2[0];
}

// ---------------- launch ----------------------------------------------------
extern "C" void kernel_launch(void* const* d_in, const int* in_sizes, int n_in,
                              void* d_out, int out_size)
{
    const float* x    = (const float*)d_in[0];
    const int*   src  = (const int*)d_in[1];
    const int*   dst  = (const int*)d_in[2];
    const int*   nsrc = (const int*)d_in[3];
    const int*   ndst = (const int*)d_in[4];
    const float* Ws1 = (const float*)d_in[5],  *Wn1 = (const float*)d_in[6],  *b1 = (const float*)d_in[7];
    const float* Ws2 = (const float*)d_in[8],  *Wn2 = (const float*)d_in[9],  *b2 = (const float*)d_in[10];
    const float* Ws3 = (const float*)d_in[11], *Wn3 = (const float*)d_in[12], *b3 = (const float*)d_in[13];
    const float* Wp1 = (const float*)d_in[14], *bp1 = (const float*)d_in[15];
    const float* Wp2 = (const float*)d_in[16], *bp2 = (const float*)d_in[17];
    float* out = (float*)d_out;

    __half *p_pa16, *p_pb16, *p_x, *p_m, *p_h1, *p_h2, *p_wh, *p_wl;
    float* p_bc;
    cudaGetSymbolAddress((void**)&p_pa16, g_pa16);
    cudaGetSymbolAddress((void**)&p_pb16, g_pb16);
    cudaGetSymbolAddress((void**)&p_x, g_x);
    cudaGetSymbolAddress((void**)&p_m, g_m);
    cudaGetSymbolAddress((void**)&p_h1, g_h1);
    cudaGetSymbolAddress((void**)&p_h2, g_h2);
    cudaGetSymbolAddress((void**)&p_wh, g_wh);
    cudaGetSymbolAddress((void**)&p_wl, g_wl);
    cudaGetSymbolAddress((void**)&p_bc, g_bc);

    cudaFuncSetAttribute(k_gemm_tc, cudaFuncAttributeMaxDynamicSharedMemorySize,
                         GEMM_SMEM);

    // --- build CSR ---
    k_zero_cnt<<<(N_NODES + 255) / 256, 256>>>();
    k_hist<<<(N_EDGES + 255) / 256, 256>>>(dst);
    k_blockscan<<<NB_SCAN, 1024>>>();
    k_scan_bsum<<<1, 128>>>();
    k_addoff<<<(N_NODES + 255) / 256, 256>>>();
    k_place<<<(N_EDGES + 255) / 256, 256>>>(src, dst);

    // --- conversions + weight composition ---
    int n4 = N_NODES * D / 4;
    k_cvt4<<<(n4 + 255) / 256, 256>>>(x, p_x, n4);
    k_cvt_w<<<(512 * D + 255) / 256, 256>>>(Ws1, Wn1, Ws2, Wn2);
    k_compose<<<512, 128>>>(Ws3, Wn3, Wp1);
    k_bias_comp<<<2, 128>>>(b3, Wp1, bp1);

    const int aggBlocks  = (N_NODES * 32 + 255) / 256;
    const int gemmBlocks = (N_NODES + 127) / 128;

    // --- layer 1 ---
    k_agg<<<aggBlocks, 256>>>(p_x);
    k_gemm_tc<<<gemmBlocks, 256, GEMM_SMEM>>>(p_x, p_m, p_wh, p_wl, b1,
                                              p_h1, nullptr, N_NODES, 256);
    // --- layer 2 ---
    k_agg<<<aggBlocks, 256>>>(p_h1);
    k_gemm_tc<<<gemmBlocks, 256, GEMM_SMEM>>>(p_h1, p_m, p_wh + 256 * D, p_wl + 256 * D, b2,
                                              p_h2, nullptr, N_NODES, 256);
    // --- layer 3 + predictor (fused via composed weights; gridDim.y=2) ---
    k_agg<<<aggBlocks, 256>>>(p_h2);
    k_gemm_tc<<<dim3(gemmBlocks, 2), 256, GEMM_SMEM>>>(
                                              p_h2, p_m, p_wh + 512 * D, p_wl + 512 * D, p_bc,
                                              p_pa16, p_pb16, N_NODES, 256);

    // --- edge scores ---
    k_edge<<<(2 * N_EDGES * 16 + 255) / 256, 256>>>(src, dst, nsrc, ndst, Wp2, bp2, out);
}

// round 11
// speedup vs baseline: 1.8752x; 1.1678x over previous
#include <cuda_runtime.h>
#include <cuda_bf16.h>
#include <cuda_fp16.h>
#include <cstdint>

#define N_NODES 100000
#define N_EDGES 640000
#define D 128
#define NB_SCAN ((N_NODES + 1023) / 1024)    // 98

// ---------------- scratch (device globals: no allocation allowed) ----------
__device__ __align__(16) __half g_pa16[N_NODES * D];
__device__ __align__(16) __half g_pb16[N_NODES * D];
// node tensors: fp16 [N][128]
__device__ __align__(16) __half g_x[N_NODES * D];
__device__ __align__(16) __half g_m[N_NODES * D];
__device__ __align__(16) __half g_h1[N_NODES * D];
__device__ __align__(16) __half g_h2[N_NODES * D];
// packed weights [K][N] fp16:
// rows [Ws1|Wn1 (0-255) | Ws2|Wn2 (256-511) | comp_pa (512-767) | comp_pb (768-1023)]
__device__ __align__(16) __half g_wh[1024 * D];
__device__ float g_bc[2 * D];                // composed predictor biases
// CSR
__device__ int g_cnt[N_NODES];
__device__ int g_rowptr[N_NODES + 1];
__device__ int g_csr[N_EDGES];
__device__ int g_bsum[NB_SCAN];
__device__ int g_boff[NB_SCAN];

// ---------------- CSR construction ----------------------------------------
__global__ void k_zero_cnt() {
    int i = blockIdx.x * blockDim.x + threadIdx.x;
    if (i < N_NODES) g_cnt[i] = 0;
}
__global__ void k_hist(const int* __restrict__ dst) {
    int e = blockIdx.x * blockDim.x + threadIdx.x;
    if (e < N_EDGES) atomicAdd(&g_cnt[dst[e]], 1);
}
__global__ void k_blockscan() {
    __shared__ int sh[1024];
    int tid = threadIdx.x;
    int i = blockIdx.x * 1024 + tid;
    int v = (i < N_NODES) ? g_cnt[i] : 0;
    sh[tid] = v;
    __syncthreads();
    for (int o = 1; o < 1024; o <<= 1) {
        int t = (tid >= o) ? sh[tid - o] : 0;
        __syncthreads();
        sh[tid] += t;
        __syncthreads();
    }
    if (i < N_NODES) g_rowptr[i] = sh[tid] - v;
    if (tid == 1023) g_bsum[blockIdx.x] = sh[1023];
}
__global__ void k_scan_bsum() {
    __shared__ int sh[128];
    int t = threadIdx.x;
    int v = (t < NB_SCAN) ? g_bsum[t] : 0;
    sh[t] = v;
    __syncthreads();
    for (int o = 1; o < 128; o <<= 1) {
        int u = (t >= o) ? sh[t - o] : 0;
        __syncthreads();
        sh[t] += u;
        __syncthreads();
    }
    if (t < NB_SCAN) g_boff[t] = sh[t] - v;
    if (t == NB_SCAN - 1) g_rowptr[N_NODES] = sh[t];
}
__global__ void k_addoff() {
    int i = blockIdx.x * blockDim.x + threadIdx.x;
    if (i < N_NODES) {
        g_rowptr[i] += g_boff[i >> 10];
        g_cnt[i] = 0;
    }
}
__global__ void k_place(const int* __restrict__ src, const int* __restrict__ dst) {
    int e = blockIdx.x * blockDim.x + threadIdx.x;
    if (e < N_EDGES) {
        int d = dst[e];
        int slot = g_rowptr[d] + atomicAdd(&g_cnt[d], 1);
        g_csr[slot] = src[e];
    }
}

// ---------------- conversions ----------------------------------------------
// x fp32 -> fp16 rows
__global__ void k_cvt4(const float* __restrict__ in, __half* __restrict__ o, int n4) {
    int i = blockIdx.x * blockDim.x + threadIdx.x;
    if (i >= n4) return;
    float4 v = ((const float4*)in)[i];
    __half2 h0 = __floats2half2_rn(v.x, v.y);
    __half2 h1 = __floats2half2_rn(v.z, v.w);
    __half2* p = (__half2*)&o[i * 4];
    p[0] = h0; p[1] = h1;
}

// layer 1/2 weights -> rows 0..511, fp16
__global__ void k_cvt_w(const float* Ws1, const float* Wn1,
                        const float* Ws2, const float* Wn2) {
    int i = blockIdx.x * blockDim.x + threadIdx.x;   // 0 .. 512*128-1
    if (i >= 512 * D) return;
    int row = i >> 7, col = i & 127;
    const float* s; int lr;
    if      (row < 128)  { s = Ws1; lr = row; }
    else if (row < 256)  { s = Wn1; lr = row - 128; }
    else if (row < 384)  { s = Ws2; lr = row - 256; }
    else                 { s = Wn2; lr = row - 384; }
    g_wh[i] = __float2half_rn(s[lr * D + col]);
}

// composed predictor weights: rows 512..1023 (fp32 compose, fp16 store)
__global__ void k_compose(const float* __restrict__ Ws3, const float* __restrict__ Wn3,
                          const float* __restrict__ Wp1) {
    int p = blockIdx.x >> 7, i = blockIdx.x & 127;
    const float* X = (p & 1) ? Wn3 : Ws3;
    const float* Y = Wp1 + ((p >> 1) ? 128 * D : 0);
    __shared__ float xr[128];
    int n = threadIdx.x;
    xr[n] = X[i * D + n];
    __syncthreads();
    float s = 0.f;
    #pragma unroll 8
    for (int k = 0; k < 128; k++) s += xr[k] * Y[k * D + n];
    int dst = ((p < 2) ? 512 : 768) + (p & 1) * 128 + i;
    g_wh[dst * D + n] = __float2half_rn(s);
}
__global__ void k_bias_comp(const float* __restrict__ b3, const float* __restrict__ Wp1,
                            const float* __restrict__ bp1) {
    int n = threadIdx.x, half = blockIdx.x;
    float s = (half == 0) ? bp1[n] : 0.f;
    for (int j = 0; j < 128; j++) s += b3[j] * Wp1[(half * 128 + j) * D + n];
    g_bc[half * D + n] = s;
}

// ---------------- mean aggregation: fp16 rows, 8 B/lane/edge ---------------
__global__ void k_agg(const __half* __restrict__ xin) {
    int gw   = (blockIdx.x * blockDim.x + threadIdx.x) >> 5;
    int lane = threadIdx.x & 31;
    if (gw >= N_NODES) return;
    int beg = g_rowptr[gw], end = g_rowptr[gw + 1];
    float acc0 = 0.f, acc1 = 0.f, acc2 = 0.f, acc3 = 0.f;
    for (int e = beg; e < end; e++) {
        const uint2 v = *(const uint2*)&xin[(size_t)g_csr[e] * D + lane * 4];
        float2 f0 = __half22float2(*(__half2*)&v.x);
        float2 f1 = __half22float2(*(__half2*)&v.y);
        acc0 += f0.x; acc1 += f0.y; acc2 += f1.x; acc3 += f1.y;
    }
    int deg = end - beg;
    float inv = 1.0f / (float)(deg > 1 ? deg : 1);
    uint2 outv;
    *(__half2*)&outv.x = __floats2half2_rn(acc0 * inv, acc1 * inv);
    *(__half2*)&outv.y = __floats2half2_rn(acc2 * inv, acc3 * inv);
    *(uint2*)&g_m[(size_t)gw * D + lane * 4] = outv;
}

// ---------------- tensor-core GEMM (fp16, 1-term, 3-stage, 2 CTA/SM) -------
__device__ __forceinline__ void ldsm4(uint32_t& r0, uint32_t& r1, uint32_t& r2,
                                      uint32_t& r3, uint32_t addr) {
    asm volatile("ldmatrix.sync.aligned.m8n8.x4.shared.b16 {%0,%1,%2,%3}, [%4];"
                 : "=r"(r0), "=r"(r1), "=r"(r2), "=r"(r3) : "r"(addr));
}
__device__ __forceinline__ void ldsm4t(uint32_t& r0, uint32_t& r1, uint32_t& r2,
                                       uint32_t& r3, uint32_t addr) {
    asm volatile("ldmatrix.sync.aligned.m8n8.x4.trans.shared.b16 {%0,%1,%2,%3}, [%4];"
                 : "=r"(r0), "=r"(r1), "=r"(r2), "=r"(r3) : "r"(addr));
}
__device__ __forceinline__ void mma_fp16(float* c, const uint32_t* a, const uint32_t* b) {
    asm volatile(
        "mma.sync.aligned.m16n8k16.row.col.f32.f16.f16.f32 "
        "{%0,%1,%2,%3},{%4,%5,%6,%7},{%8,%9},{%0,%1,%2,%3};"
        : "+f"(c[0]), "+f"(c[1]), "+f"(c[2]), "+f"(c[3])
        : "r"(a[0]), "r"(a[1]), "r"(a[2]), "r"(a[3]), "r"(b[0]), "r"(b[1]));
}
__device__ __forceinline__ void cp16(uint32_t s, const void* g, bool p) {
    asm volatile("cp.async.cg.shared.global [%0], [%1], 16, %2;"
                 :: "r"(s), "l"(g), "r"(p ? 16 : 0));
}

#define A_STRIDE 80u
#define B_STRIDE 272u
#define A_BYTES (128u * A_STRIDE)            // 10240
#define B_BYTES (32u * B_STRIDE)             // 8704
#define STAGE (A_BYTES + B_BYTES)            // 18944
#define GEMM_SMEM (3 * STAGE)                // 56832 -> 2 CTAs/SM

// out[M,128] = (A1|A2)[M,K=256] @ W[K,128] + bias ; fp16.
// If pred (gridDim.y==2): y==1 selects W+256 rows, bias+128, out=outB.
__global__ __launch_bounds__(256, 2) void k_gemm_tc(
    const __half* __restrict__ A1, const __half* __restrict__ A2,
    const __half* __restrict__ Wh,
    const float* __restrict__ bias,
    __half* __restrict__ outA, __half* __restrict__ outB,
    int M, int K)
{
    extern __shared__ char smdyn[];
    uint32_t base = (uint32_t)__cvta_generic_to_shared(smdyn);

    __half* outp = outA;
    if (outB && blockIdx.y == 1) {
        Wh += 256 * D; bias += 128; outp = outB;
    }

    int tid = threadIdx.x;
    int wid = tid >> 5, lane = tid & 31;
    int warp_m = (wid >> 2) * 64;
    int warp_n = (wid & 3) * 32;
    int m0 = blockIdx.x * 128;
    int nch = K / 32;

    float c[4][4][4];
    #pragma unroll
    for (int i = 0; i < 4; i++)
        #pragma unroll
        for (int j = 0; j < 4; j++)
            #pragma unroll
            for (int q = 0; q < 4; q++) c[i][j][q] = 0.f;

    auto load_chunk = [&](int ch) {
        uint32_t st = base + (uint32_t)(ch % 3) * STAGE;
        int kb = ch * 32;
        const __half* A = (kb < 128) ? A1 : A2;
        int ac = kb & 127;
        #pragma unroll
        for (int l = tid; l < 512; l += 256) {      // A: 128 rows x 4 segs(16B)
            int r = l >> 2, seg = l & 3;
            uint32_t so = (uint32_t)r * A_STRIDE + (uint32_t)seg * 16u;
            bool p = (m0 + r) < M;
            int rr = p ? (m0 + r) : 0;
            cp16(st + so, A + (size_t)rr * D + ac + seg * 8, p);
        }
        #pragma unroll
        for (int l = tid; l < 512; l += 256) {      // B: 32 rows x 16 segs
            int r = l >> 4, seg = l & 15;
            uint32_t so = (uint32_t)r * B_STRIDE + (uint32_t)seg * 16u;
            cp16(st + A_BYTES + so, Wh + (size_t)(kb + r) * D + seg * 8, true);
        }
        asm volatile("cp.async.commit_group;" ::: "memory");
    };

    load_chunk(0);
    load_chunk(1);

    int lr = (lane & 7) + 8 * ((lane >> 3) & 1);
    int lc = 8 * (lane >> 4);

    for (int ch = 0; ch < nch; ch++) {
        if (ch + 1 < nch) {
            asm volatile("cp.async.wait_group 1;" ::: "memory");
        } else {
            asm volatile("cp.async.wait_group 0;" ::: "memory");
        }
        __syncthreads();     // single barrier: orders stage reuse + visibility
        if (ch + 2 < nch) load_chunk(ch + 2);

        uint32_t st  = base + (uint32_t)(ch % 3) * STAGE;
        uint32_t a_b = st;
        uint32_t b_b = st + A_BYTES;

        #pragma unroll
        for (int ks = 0; ks < 2; ks++) {
            int k0 = ks * 16;
            uint32_t a[4][4];
            #pragma unroll
            for (int mi = 0; mi < 4; mi++) {
                uint32_t ro = (uint32_t)(warp_m + mi * 16 + lr) * A_STRIDE
                            + (uint32_t)(k0 + lc) * 2u;
                ldsm4(a[mi][0], a[mi][1], a[mi][2], a[mi][3], a_b + ro);
            }
            uint32_t b[4][2];
            #pragma unroll
            for (int njp = 0; njp < 2; njp++) {
                uint32_t ro = (uint32_t)(k0 + lr) * B_STRIDE
                            + (uint32_t)(warp_n + njp * 16 + lc) * 2u;
                uint32_t r0, r1, r2, r3;
                ldsm4t(r0, r1, r2, r3, b_b + ro);
                b[2 * njp][0] = r0;     b[2 * njp][1] = r1;
                b[2 * njp + 1][0] = r2; b[2 * njp + 1][1] = r3;
            }
            #pragma unroll
            for (int mi = 0; mi < 4; mi++)
                #pragma unroll
                for (int nj = 0; nj < 4; nj++)
                    mma_fp16(c[mi][nj], a[mi], b[nj]);
        }
    }

    // epilogue: fp16 output
    #pragma unroll
    for (int mi = 0; mi < 4; mi++) {
        #pragma unroll
        for (int nj = 0; nj < 4; nj++) {
            int row0 = m0 + warp_m + mi * 16 + (lane >> 2);
            int col  = warp_n + nj * 8 + (lane & 3) * 2;
            float b0 = bias ? bias[col] : 0.f;
            float b1 = bias ? bias[col + 1] : 0.f;
            #pragma unroll
            for (int h = 0; h < 2; h++) {
                int row = row0 + 8 * h;
                if (row < M) {
                    float v0 = c[mi][nj][2 * h]     + b0;
                    float v1 = c[mi][nj][2 * h + 1] + b1;
                    *(__half2*)&outp[(size_t)row * D + col] =
                        __floats2half2_rn(v0, v1);
                }
            }
        }
    }
}

// ---------------- edge scoring (fp16 projections, 16 lanes/edge) ------------
__global__ void k_edge(const int* __restrict__ s1, const int* __restrict__ d1,
                       const int* __restrict__ s2, const int* __restrict__ d2,
                       const float* __restrict__ Wp2, const float* __restrict__ bp2,
                       float* __restrict__ out)
{
    int g = blockIdx.x * blockDim.x + threadIdx.x;
    int e = g >> 4, lane16 = g & 15;
    if (e >= 2 * N_EDGES) return;
    int ss, dd;
    if (e < N_EDGES) { ss = s1[e]; dd = d1[e]; }
    else             { ss = s2[e - N_EDGES]; dd = d2[e - N_EDGES]; }

    uint4 av = *(const uint4*)&g_pa16[(size_t)ss * D + lane16 * 8];
    uint4 bv = *(const uint4*)&g_pb16[(size_t)dd * D + lane16 * 8];
    float4 w0 = *(const float4*)&Wp2[lane16 * 8];
    float4 w1 = *(const float4*)&Wp2[lane16 * 8 + 4];

    float2 a0 = __half22float2(*(__half2*)&av.x);
    float2 a1 = __half22float2(*(__half2*)&av.y);
    float2 a2 = __half22float2(*(__half2*)&av.z);
    float2 a3 = __half22float2(*(__half2*)&av.w);
    float2 b0 = __half22float2(*(__half2*)&bv.x);
    float2 b1 = __half22float2(*(__half2*)&bv.y);
    float2 b2 = __half22float2(*(__half2*)&bv.z);
    float2 b3 = __half22float2(*(__half2*)&bv.w);

    float p = fmaxf(a0.x + b0.x, 0.f) * w0.x
            + fmaxf(a0.y + b0.y, 0.f) * w0.y
            + fmaxf(a1.x + b1.x, 0.f) * w0.z
            + fmaxf(a1.y + b1.y, 0.f) * w0.w
            + fmaxf(a2.x + b2.x, 0.f) * w1.x
            + fmaxf(a2.y + b2.y, 0.f) * w1.y
            + fmaxf(a3.x + b3.x, 0.f) * w1.z
            + fmaxf(a3.y + b3.y, 0.f) * w1.w;
    #pragma unroll
    for (int o = 8; o > 0; o >>= 1) p += __shfl_xor_sync(0xffffffffu, p, o);
    if (lane16 == 0) out[e] = p + bp2[0];
}

// ---------------- launch ----------------------------------------------------
extern "C" void kernel_launch(void* const* d_in, const int* in_sizes, int n_in,
                              void* d_out, int out_size)
{
    const float* x    = (const float*)d_in[0];
    const int*   src  = (const int*)d_in[1];
    const int*   dst  = (const int*)d_in[2];
    const int*   nsrc = (const int*)d_in[3];
    const int*   ndst = (const int*)d_in[4];
    const float* Ws1 = (const float*)d_in[5],  *Wn1 = (const float*)d_in[6],  *b1 = (const float*)d_in[7];
    const float* Ws2 = (const float*)d_in[8],  *Wn2 = (const float*)d_in[9],  *b2 = (const float*)d_in[10];
    const float* Ws3 = (const float*)d_in[11], *Wn3 = (const float*)d_in[12], *b3 = (const float*)d_in[13];
    const float* Wp1 = (const float*)d_in[14], *bp1 = (const float*)d_in[15];
    const float* Wp2 = (const float*)d_in[16], *bp2 = (const float*)d_in[17];
    float* out = (float*)d_out;

    __half *p_pa16, *p_pb16, *p_x, *p_m, *p_h1, *p_h2, *p_wh;
    float* p_bc;
    cudaGetSymbolAddress((void**)&p_pa16, g_pa16);
    cudaGetSymbolAddress((void**)&p_pb16, g_pb16);
    cudaGetSymbolAddress((void**)&p_x, g_x);
    cudaGetSymbolAddress((void**)&p_m, g_m);
    cudaGetSymbolAddress((void**)&p_h1, g_h1);
    cudaGetSymbolAddress((void**)&p_h2, g_h2);
    cudaGetSymbolAddress((void**)&p_wh, g_wh);
    cudaGetSymbolAddress((void**)&p_bc, g_bc);

    cudaFuncSetAttribute(k_gemm_tc, cudaFuncAttributeMaxDynamicSharedMemorySize,
                         GEMM_SMEM);

    // --- build CSR ---
    k_zero_cnt<<<(N_NODES + 255) / 256, 256>>>();
    k_hist<<<(N_EDGES + 255) / 256, 256>>>(dst);
    k_blockscan<<<NB_SCAN, 1024>>>();
    k_scan_bsum<<<1, 128>>>();
    k_addoff<<<(N_NODES + 255) / 256, 256>>>();
    k_place<<<(N_EDGES + 255) / 256, 256>>>(src, dst);

    // --- conversions + weight composition ---
    int n4 = N_NODES * D / 4;
    k_cvt4<<<(n4 + 255) / 256, 256>>>(x, p_x, n4);
    k_cvt_w<<<(512 * D + 255) / 256, 256>>>(Ws1, Wn1, Ws2, Wn2);
    k_compose<<<512, 128>>>(Ws3, Wn3, Wp1);
    k_bias_comp<<<2, 128>>>(b3, Wp1, bp1);

    const int aggBlocks  = (N_NODES * 32 + 255) / 256;
    const int gemmBlocks = (N_NODES + 127) / 128;

    // --- layer 1 ---
    k_agg<<<aggBlocks, 256>>>(p_x);
    k_gemm_tc<<<gemmBlocks, 256, GEMM_SMEM>>>(p_x, p_m, p_wh, b1,
                                              p_h1, nullptr, N_NODES, 256);
    // --- layer 2 ---
    k_agg<<<aggBlocks, 256>>>(p_h1);
    k_gemm_tc<<<gemmBlocks, 256, GEMM_SMEM>>>(p_h1, p_m, p_wh + 256 * D, b2,
                                              p_h2, nullptr, N_NODES, 256);
    // --- layer 3 + predictor (fused via composed weights; gridDim.y=2) ---
    k_agg<<<aggBlocks, 256>>>(p_h2);
    k_gemm_tc<<<dim3(gemmBlocks, 2), 256, GEMM_SMEM>>>(
                                              p_h2, p_m, p_wh + 512 * D, p_bc,
                                              p_pa16, p_pb16, N_NODES, 256);

    // --- edge scores ---
    k_edge<<<(2 * N_EDGES * 16 + 255) / 256, 256>>>(src, dst, nsrc, ndst, Wp2, bp2, out);
}

// round 12
// speedup vs baseline: 1.9422x; 1.0357x over previous
#include <cuda_runtime.h>
#include <cuda_bf16.h>
#include <cuda_fp16.h>
#include <cstdint>

#define N_NODES 100000
#define N_EDGES 640000
#define D 128
#define NB_SCAN ((N_NODES + 1023) / 1024)    // 98

// ---------------- scratch (device globals: no allocation allowed) ----------
__device__ __align__(16) __half g_pa16[N_NODES * D];
__device__ __align__(16) __half g_pb16[N_NODES * D];
// node tensors: fp16 [N][128]
__device__ __align__(16) __half g_x[N_NODES * D];
__device__ __align__(16) __half g_m[N_NODES * D];
__device__ __align__(16) __half g_h1[N_NODES * D];
__device__ __align__(16) __half g_h2[N_NODES * D];
// packed weights [K][N] fp16:
// rows [Ws1|Wn1 (0-255) | Ws2|Wn2 (256-511) | comp_pa (512-767) | comp_pb (768-1023)]
__device__ __align__(16) __half g_wh[1024 * D];
__device__ float g_bc[2 * D];                // composed predictor biases
// CSR
__device__ int g_cnt[N_NODES];
__device__ int g_rowptr[N_NODES + 1];
__device__ int g_csr[N_EDGES];
__device__ int g_bsum[NB_SCAN];
__device__ int g_ready[NB_SCAN];

// ---------------- CSR construction ----------------------------------------
__global__ void k_hist(const int* __restrict__ dst) {
    int e = blockIdx.x * blockDim.x + threadIdx.x;
    if (e < N_EDGES) atomicAdd(&g_cnt[dst[e]], 1);
}

// fused scan: per-block scan + decoupled aggregate lookback + rowptr + cnt reset
__global__ void k_scan_fused() {
    __shared__ int sh[1024];
    __shared__ int red[32];
    int tid = threadIdx.x, blk = blockIdx.x;
    int i = blk * 1024 + tid;
    int v = (i < N_NODES) ? g_cnt[i] : 0;
    sh[tid] = v;
    __syncthreads();
    for (int o = 1; o < 1024; o <<= 1) {
        int t = (tid >= o) ? sh[tid - o] : 0;
        __syncthreads();
        sh[tid] += t;
        __syncthreads();
    }
    int total = sh[1023];
    if (tid == 0) {
        *(volatile int*)&g_bsum[blk] = total;
        __threadfence();
        *(volatile int*)&g_ready[blk] = 1;
    }
    // sum predecessor aggregates (all blocks resident: spin is safe)
    int myv = 0;
    for (int j = tid; j < blk; j += 1024) {
        while (*(volatile int*)&g_ready[j] == 0) {}
        myv += *(volatile int*)&g_bsum[j];
    }
    #pragma unroll
    for (int o = 16; o > 0; o >>= 1) myv += __shfl_xor_sync(0xffffffffu, myv, o);
    if ((tid & 31) == 0) red[tid >> 5] = myv;
    __syncthreads();
    if (tid == 0) {
        int s = 0;
        #pragma unroll
        for (int w = 0; w < 32; w++) s += red[w];
        red[0] = s;
    }
    __syncthreads();
    int pref = red[0];
    if (i < N_NODES) {
        g_rowptr[i] = pref + sh[tid] - v;    // global exclusive
        g_cnt[i] = 0;                        // reset for k_place
    }
    if (blk == NB_SCAN - 1 && tid == 1023) g_rowptr[N_NODES] = pref + total;
}

__global__ void k_place(const int* __restrict__ src, const int* __restrict__ dst) {
    int e = blockIdx.x * blockDim.x + threadIdx.x;
    if (e < N_EDGES) {
        int d = dst[e];
        int slot = g_rowptr[d] + atomicAdd(&g_cnt[d], 1);
        g_csr[slot] = src[e];
    }
}

// ---------------- conversions ----------------------------------------------
// x fp32 -> fp16 rows; also zeroes g_cnt and g_ready (fused init)
__global__ void k_cvt4(const float* __restrict__ in, __half* __restrict__ o, int n4) {
    int i = blockIdx.x * blockDim.x + threadIdx.x;
    if (i < N_NODES) g_cnt[i] = 0;
    if (i < NB_SCAN) g_ready[i] = 0;
    if (i >= n4) return;
    float4 v = ((const float4*)in)[i];
    __half2 h0 = __floats2half2_rn(v.x, v.y);
    __half2 h1 = __floats2half2_rn(v.z, v.w);
    __half2* p = (__half2*)&o[i * 4];
    p[0] = h0; p[1] = h1;
}

// fused weight prep: blocks [0,256) cvt Ws1|Wn1|Ws2|Wn2; [256,512) compose;
// block 512: composed biases. All 256 threads/block.
__global__ void k_wprep(const float* __restrict__ Ws1, const float* __restrict__ Wn1,
                        const float* __restrict__ Ws2, const float* __restrict__ Wn2,
                        const float* __restrict__ Ws3, const float* __restrict__ Wn3,
                        const float* __restrict__ Wp1, const float* __restrict__ b3,
                        const float* __restrict__ bp1) {
    int blk = blockIdx.x, tid = threadIdx.x;
    if (blk < 256) {                              // layer 1/2 weights, rows 0..511
        int i = blk * 256 + tid;                  // 0 .. 65535
        int row = i >> 7, col = i & 127;
        const float* s; int lr;
        if      (row < 128)  { s = Ws1; lr = row; }
        else if (row < 256)  { s = Wn1; lr = row - 128; }
        else if (row < 384)  { s = Ws2; lr = row - 256; }
        else                 { s = Wn2; lr = row - 384; }
        g_wh[i] = __float2half_rn(s[lr * D + col]);
    } else if (blk < 512) {                       // composed predictor weights
        __shared__ float xr[2][128];
        int idx = (blk - 256) * 2 + (tid >> 7);   // 0..511 = p*128 + i
        int p = idx >> 7, i = idx & 127;
        int sub = tid >> 7, n = tid & 127;
        const float* X = (p & 1) ? Wn3 : Ws3;
        const float* Y = Wp1 + ((p >> 1) ? 128 * D : 0);
        xr[sub][n] = X[i * D + n];
        __syncthreads();
        float s = 0.f;
        #pragma unroll 8
        for (int k = 0; k < 128; k++) s += xr[sub][k] * Y[k * D + n];
        int dst = ((p < 2) ? 512 : 768) + (p & 1) * 128 + i;
        g_wh[dst * D + n] = __float2half_rn(s);
    } else {                                      // composed biases
        int half = tid >> 7, n = tid & 127;
        float s = (half == 0) ? bp1[n] : 0.f;
        for (int j = 0; j < 128; j++) s += b3[j] * Wp1[(half * 128 + j) * D + n];
        g_bc[half * D + n] = s;
    }
}

// ---------------- mean aggregation: half-warp/node, 16 B loads -------------
__global__ void k_agg(const __half* __restrict__ xin) {
    int g = blockIdx.x * blockDim.x + threadIdx.x;
    int node = g >> 4, lane16 = g & 15;
    if (node >= N_NODES) return;
    int beg = g_rowptr[node], end = g_rowptr[node + 1];
    float a0 = 0.f, a1 = 0.f, a2 = 0.f, a3 = 0.f;
    float a4 = 0.f, a5 = 0.f, a6 = 0.f, a7 = 0.f;
    for (int e = beg; e < end; e++) {
        const uint4 v = *(const uint4*)&xin[(size_t)g_csr[e] * D + lane16 * 8];
        float2 f0 = __half22float2(*(__half2*)&v.x);
        float2 f1 = __half22float2(*(__half2*)&v.y);
        float2 f2 = __half22float2(*(__half2*)&v.z);
        float2 f3 = __half22float2(*(__half2*)&v.w);
        a0 += f0.x; a1 += f0.y; a2 += f1.x; a3 += f1.y;
        a4 += f2.x; a5 += f2.y; a6 += f3.x; a7 += f3.y;
    }
    int deg = end - beg;
    float inv = 1.0f / (float)(deg > 1 ? deg : 1);
    uint4 outv;
    *(__half2*)&outv.x = __floats2half2_rn(a0 * inv, a1 * inv);
    *(__half2*)&outv.y = __floats2half2_rn(a2 * inv, a3 * inv);
    *(__half2*)&outv.z = __floats2half2_rn(a4 * inv, a5 * inv);
    *(__half2*)&outv.w = __floats2half2_rn(a6 * inv, a7 * inv);
    *(uint4*)&g_m[(size_t)node * D + lane16 * 8] = outv;
}

// ---------------- tensor-core GEMM (fp16, 1-term, 3-stage, 2 CTA/SM) -------
__device__ __forceinline__ void ldsm4(uint32_t& r0, uint32_t& r1, uint32_t& r2,
                                      uint32_t& r3, uint32_t addr) {
    asm volatile("ldmatrix.sync.aligned.m8n8.x4.shared.b16 {%0,%1,%2,%3}, [%4];"
                 : "=r"(r0), "=r"(r1), "=r"(r2), "=r"(r3) : "r"(addr));
}
__device__ __forceinline__ void ldsm4t(uint32_t& r0, uint32_t& r1, uint32_t& r2,
                                       uint32_t& r3, uint32_t addr) {
    asm volatile("ldmatrix.sync.aligned.m8n8.x4.trans.shared.b16 {%0,%1,%2,%3}, [%4];"
                 : "=r"(r0), "=r"(r1), "=r"(r2), "=r"(r3) : "r"(addr));
}
__device__ __forceinline__ void mma_fp16(float* c, const uint32_t* a, const uint32_t* b) {
    asm volatile(
        "mma.sync.aligned.m16n8k16.row.col.f32.f16.f16.f32 "
        "{%0,%1,%2,%3},{%4,%5,%6,%7},{%8,%9},{%0,%1,%2,%3};"
        : "+f"(c[0]), "+f"(c[1]), "+f"(c[2]), "+f"(c[3])
        : "r"(a[0]), "r"(a[1]), "r"(a[2]), "r"(a[3]), "r"(b[0]), "r"(b[1]));
}
__device__ __forceinline__ void cp16(uint32_t s, const void* g, bool p) {
    asm volatile("cp.async.cg.shared.global [%0], [%1], 16, %2;"
                 :: "r"(s), "l"(g), "r"(p ? 16 : 0));
}

#define A_STRIDE 80u
#define B_STRIDE 272u
#define A_BYTES (128u * A_STRIDE)            // 10240
#define B_BYTES (32u * B_STRIDE)             // 8704
#define STAGE (A_BYTES + B_BYTES)            // 18944
#define GEMM_SMEM (3 * STAGE)                // 56832 -> 2 CTAs/SM

// out[M,128] = (A1|A2)[M,K=256] @ W[K,128] + bias ; fp16.
// If pred (gridDim.y==2): y==1 selects W+256 rows, bias+128, out=outB.
__global__ __launch_bounds__(256, 2) void k_gemm_tc(
    const __half* __restrict__ A1, const __half* __restrict__ A2,
    const __half* __restrict__ Wh,
    const float* __restrict__ bias,
    __half* __restrict__ outA, __half* __restrict__ outB,
    int M, int K)
{
    extern __shared__ char smdyn[];
    uint32_t base = (uint32_t)__cvta_generic_to_shared(smdyn);

    __half* outp = outA;
    if (outB && blockIdx.y == 1) {
        Wh += 256 * D; bias += 128; outp = outB;
    }

    int tid = threadIdx.x;
    int wid = tid >> 5, lane = tid & 31;
    int warp_m = (wid >> 2) * 64;
    int warp_n = (wid & 3) * 32;
    int m0 = blockIdx.x * 128;
    int nch = K / 32;

    float c[4][4][4];
    #pragma unroll
    for (int i = 0; i < 4; i++)
        #pragma unroll
        for (int j = 0; j < 4; j++)
            #pragma unroll
            for (int q = 0; q < 4; q++) c[i][j][q] = 0.f;

    auto load_chunk = [&](int ch) {
        uint32_t st = base + (uint32_t)(ch % 3) * STAGE;
        int kb = ch * 32;
        const __half* A = (kb < 128) ? A1 : A2;
        int ac = kb & 127;
        #pragma unroll
        for (int l = tid; l < 512; l += 256) {      // A: 128 rows x 4 segs(16B)
            int r = l >> 2, seg = l & 3;
            uint32_t so = (uint32_t)r * A_STRIDE + (uint32_t)seg * 16u;
            bool p = (m0 + r) < M;
            int rr = p ? (m0 + r) : 0;
            cp16(st + so, A + (size_t)rr * D + ac + seg * 8, p);
        }
        #pragma unroll
        for (int l = tid; l < 512; l += 256) {      // B: 32 rows x 16 segs
            int r = l >> 4, seg = l & 15;
            uint32_t so = (uint32_t)r * B_STRIDE + (uint32_t)seg * 16u;
            cp16(st + A_BYTES + so, Wh + (size_t)(kb + r) * D + seg * 8, true);
        }
        asm volatile("cp.async.commit_group;" ::: "memory");
    };

    load_chunk(0);
    load_chunk(1);

    int lr = (lane & 7) + 8 * ((lane >> 3) & 1);
    int lc = 8 * (lane >> 4);

    for (int ch = 0; ch < nch; ch++) {
        if (ch + 1 < nch) {
            asm volatile("cp.async.wait_group 1;" ::: "memory");
        } else {
            asm volatile("cp.async.wait_group 0;" ::: "memory");
        }
        __syncthreads();     // single barrier: orders stage reuse + visibility
        if (ch + 2 < nch) load_chunk(ch + 2);

        uint32_t st  = base + (uint32_t)(ch % 3) * STAGE;
        uint32_t a_b = st;
        uint32_t b_b = st + A_BYTES;

        #pragma unroll
        for (int ks = 0; ks < 2; ks++) {
            int k0 = ks * 16;
            uint32_t a[4][4];
            #pragma unroll
            for (int mi = 0; mi < 4; mi++) {
                uint32_t ro = (uint32_t)(warp_m + mi * 16 + lr) * A_STRIDE
                            + (uint32_t)(k0 + lc) * 2u;
                ldsm4(a[mi][0], a[mi][1], a[mi][2], a[mi][3], a_b + ro);
            }
            uint32_t b[4][2];
            #pragma unroll
            for (int njp = 0; njp < 2; njp++) {
                uint32_t ro = (uint32_t)(k0 + lr) * B_STRIDE
                            + (uint32_t)(warp_n + njp * 16 + lc) * 2u;
                uint32_t r0, r1, r2, r3;
                ldsm4t(r0, r1, r2, r3, b_b + ro);
                b[2 * njp][0] = r0;     b[2 * njp][1] = r1;
                b[2 * njp + 1][0] = r2; b[2 * njp + 1][1] = r3;
            }
            #pragma unroll
            for (int mi = 0; mi < 4; mi++)
                #pragma unroll
                for (int nj = 0; nj < 4; nj++)
                    mma_fp16(c[mi][nj], a[mi], b[nj]);
        }
    }

    // epilogue: fp16 output
    #pragma unroll
    for (int mi = 0; mi < 4; mi++) {
        #pragma unroll
        for (int nj = 0; nj < 4; nj++) {
            int row0 = m0 + warp_m + mi * 16 + (lane >> 2);
            int col  = warp_n + nj * 8 + (lane & 3) * 2;
            float b0 = bias ? bias[col] : 0.f;
            float b1 = bias ? bias[col + 1] : 0.f;
            #pragma unroll
            for (int h = 0; h < 2; h++) {
                int row = row0 + 8 * h;
                if (row < M) {
                    float v0 = c[mi][nj][2 * h]     + b0;
                    float v1 = c[mi][nj][2 * h + 1] + b1;
                    *(__half2*)&outp[(size_t)row * D + col] =
                        __floats2half2_rn(v0, v1);
                }
            }
        }
    }
}

// ---------------- edge scoring (fp16 projections, 16 lanes/edge) ------------
__global__ void k_edge(const int* __restrict__ s1, const int* __restrict__ d1,
                       const int* __restrict__ s2, const int* __restrict__ d2,
                       const float* __restrict__ Wp2, const float* __restrict__ bp2,
                       float* __restrict__ out)
{
    int g = blockIdx.x * blockDim.x + threadIdx.x;
    int e = g >> 4, lane16 = g & 15;
    if (e >= 2 * N_EDGES) return;
    int ss, dd;
    if (e < N_EDGES) { ss = s1[e]; dd = d1[e]; }
    else             { ss = s2[e - N_EDGES]; dd = d2[e - N_EDGES]; }

    uint4 av = *(const uint4*)&g_pa16[(size_t)ss * D + lane16 * 8];
    uint4 bv = *(const uint4*)&g_pb16[(size_t)dd * D + lane16 * 8];
    float4 w0 = *(const float4*)&Wp2[lane16 * 8];
    float4 w1 = *(const float4*)&Wp2[lane16 * 8 + 4];

    float2 a0 = __half22float2(*(__half2*)&av.x);
    float2 a1 = __half22float2(*(__half2*)&av.y);
    float2 a2 = __half22float2(*(__half2*)&av.z);
    float2 a3 = __half22float2(*(__half2*)&av.w);
    float2 b0 = __half22float2(*(__half2*)&bv.x);
    float2 b1 = __half22float2(*(__half2*)&bv.y);
    float2 b2 = __half22float2(*(__half2*)&bv.z);
    float2 b3 = __half22float2(*(__half2*)&bv.w);

    float p = fmaxf(a0.x + b0.x, 0.f) * w0.x
            + fmaxf(a0.y + b0.y, 0.f) * w0.y
            + fmaxf(a1.x + b1.x, 0.f) * w0.z
            + fmaxf(a1.y + b1.y, 0.f) * w0.w
            + fmaxf(a2.x + b2.x, 0.f) * w1.x
            + fmaxf(a2.y + b2.y, 0.f) * w1.y
            + fmaxf(a3.x + b3.x, 0.f) * w1.z
            + fmaxf(a3.y + b3.y, 0.f) * w1.w;
    #pragma unroll
    for (int o = 8; o > 0; o >>= 1) p += __shfl_xor_sync(0xffffffffu, p, o);
    if (lane16 == 0) out[e] = p + bp2[0];
}

// ---------------- launch ----------------------------------------------------
extern "C" void kernel_launch(void* const* d_in, const int* in_sizes, int n_in,
                              void* d_out, int out_size)
{
    const float* x    = (const float*)d_in[0];
    const int*   src  = (const int*)d_in[1];
    const int*   dst  = (const int*)d_in[2];
    const int*   nsrc = (const int*)d_in[3];
    const int*   ndst = (const int*)d_in[4];
    const float* Ws1 = (const float*)d_in[5],  *Wn1 = (const float*)d_in[6],  *b1 = (const float*)d_in[7];
    const float* Ws2 = (const float*)d_in[8],  *Wn2 = (const float*)d_in[9],  *b2 = (const float*)d_in[10];
    const float* Ws3 = (const float*)d_in[11], *Wn3 = (const float*)d_in[12], *b3 = (const float*)d_in[13];
    const float* Wp1 = (const float*)d_in[14], *bp1 = (const float*)d_in[15];
    const float* Wp2 = (const float*)d_in[16], *bp2 = (const float*)d_in[17];
    float* out = (float*)d_out;

    __half *p_pa16, *p_pb16, *p_x, *p_m, *p_h1, *p_h2, *p_wh;
    float* p_bc;
    cudaGetSymbolAddress((void**)&p_pa16, g_pa16);
    cudaGetSymbolAddress((void**)&p_pb16, g_pb16);
    cudaGetSymbolAddress((void**)&p_x, g_x);
    cudaGetSymbolAddress((void**)&p_m, g_m);
    cudaGetSymbolAddress((void**)&p_h1, g_h1);
    cudaGetSymbolAddress((void**)&p_h2, g_h2);
    cudaGetSymbolAddress((void**)&p_wh, g_wh);
    cudaGetSymbolAddress((void**)&p_bc, g_bc);

    cudaFuncSetAttribute(k_gemm_tc, cudaFuncAttributeMaxDynamicSharedMemorySize,
                         GEMM_SMEM);

    int n4 = N_NODES * D / 4;

    // --- init + x conversion (zeroes cnt/ready) ---
    k_cvt4<<<(n4 + 255) / 256, 256>>>(x, p_x, n4);
    // --- build CSR (3 launches) ---
    k_hist<<<(N_EDGES + 255) / 256, 256>>>(dst);
    k_scan_fused<<<NB_SCAN, 1024>>>();
    k_place<<<(N_EDGES + 255) / 256, 256>>>(src, dst);
    // --- weight prep (1 launch) ---
    k_wprep<<<513, 256>>>(Ws1, Wn1, Ws2, Wn2, Ws3, Wn3, Wp1, b3, bp1);

    const int aggBlocks  = (N_NODES * 16 + 255) / 256;
    const int gemmBlocks = (N_NODES + 127) / 128;

    // --- layer 1 ---
    k_agg<<<aggBlocks, 256>>>(p_x);
    k_gemm_tc<<<gemmBlocks, 256, GEMM_SMEM>>>(p_x, p_m, p_wh, b1,
                                              p_h1, nullptr, N_NODES, 256);
    // --- layer 2 ---
    k_agg<<<aggBlocks, 256>>>(p_h1);
    k_gemm_tc<<<gemmBlocks, 256, GEMM_SMEM>>>(p_h1, p_m, p_wh + 256 * D, b2,
                                              p_h2, nullptr, N_NODES, 256);
    // --- layer 3 + predictor (fused via composed weights; gridDim.y=2) ---
    k_agg<<<aggBlocks, 256>>>(p_h2);
    k_gemm_tc<<<dim3(gemmBlocks, 2), 256, GEMM_SMEM>>>(
                                              p_h2, p_m, p_wh + 512 * D, p_bc,
                                              p_pa16, p_pb16, N_NODES, 256);

    // --- edge scores ---
    k_edge<<<(2 * N_EDGES * 16 + 255) / 256, 256>>>(src, dst, nsrc, ndst, Wp2, bp2, out);
}

// round 13
// speedup vs baseline: 1.9911x; 1.0252x over previous
#include <cuda_runtime.h>
#include <cuda_bf16.h>
#include <cuda_fp16.h>
#include <cstdint>

#define N_NODES 100000
#define N_EDGES 640000
#define D 128
#define NB_SCAN ((N_NODES + 1023) / 1024)    // 98

#define CVT_BLOCKS 12500                     // N_NODES*D/4 / 256
#define HIST_BLOCKS 2500                     // N_EDGES / 256
#define WPREP_BLOCKS 513

// ---------------- scratch (device globals: zero at module load) ------------
__device__ __align__(16) __half g_pa16[N_NODES * D];
__device__ __align__(16) __half g_pb16[N_NODES * D];
// node tensors: fp16 [N][128]
__device__ __align__(16) __half g_x[N_NODES * D];
__device__ __align__(16) __half g_m[N_NODES * D];
__device__ __align__(16) __half g_h1[N_NODES * D];
__device__ __align__(16) __half g_h2[N_NODES * D];
// packed weights [K][N] fp16:
// rows [Ws1|Wn1 (0-255) | Ws2|Wn2 (256-511) | comp_pa (512-767) | comp_pb (768-1023)]
__device__ __align__(16) __half g_wh[1024 * D];
__device__ float g_bc[2 * D];                // composed predictor biases
// CSR  (INVARIANT: g_cnt == 0 and g_ready == 0 at kernel_launch entry;
//       k_edge restores this at the end of every launch)
__device__ int g_cnt[N_NODES];
__device__ int g_rowptr[N_NODES + 1];
__device__ int g_csr[N_EDGES];
__device__ int g_bsum[NB_SCAN];
__device__ int g_ready[NB_SCAN];

// ---------------- fused prologue: x-cvt + dst-hist + weight prep -----------
__global__ void k_prep(const float* __restrict__ x, __half* __restrict__ xo,
                       const int* __restrict__ dst,
                       const float* __restrict__ Ws1, const float* __restrict__ Wn1,
                       const float* __restrict__ Ws2, const float* __restrict__ Wn2,
                       const float* __restrict__ Ws3, const float* __restrict__ Wn3,
                       const float* __restrict__ Wp1, const float* __restrict__ b3,
                       const float* __restrict__ bp1) {
    int blk = blockIdx.x, tid = threadIdx.x;
    if (blk < CVT_BLOCKS) {                       // ---- x fp32 -> fp16
        int i = blk * 256 + tid;                  // < 3.2M exactly
        float4 v = ((const float4*)x)[i];
        __half2* p = (__half2*)&xo[i * 4];
        p[0] = __floats2half2_rn(v.x, v.y);
        p[1] = __floats2half2_rn(v.z, v.w);
    } else if (blk < CVT_BLOCKS + HIST_BLOCKS) {  // ---- degree histogram
        int e = (blk - CVT_BLOCKS) * 256 + tid;
        if (e < N_EDGES) atomicAdd(&g_cnt[dst[e]], 1);
    } else {                                      // ---- weight prep
        int wb = blk - CVT_BLOCKS - HIST_BLOCKS;  // 0..512
        if (wb < 256) {                           // layer 1/2 weights
            int i = wb * 256 + tid;
            int row = i >> 7, col = i & 127;
            const float* s; int lr;
            if      (row < 128)  { s = Ws1; lr = row; }
            else if (row < 256)  { s = Wn1; lr = row - 128; }
            else if (row < 384)  { s = Ws2; lr = row - 256; }
            else                 { s = Wn2; lr = row - 384; }
            g_wh[i] = __float2half_rn(s[lr * D + col]);
        } else if (wb < 512) {                    // composed predictor weights
            __shared__ float xr[2][128];
            int idx = (wb - 256) * 2 + (tid >> 7);
            int p = idx >> 7, i = idx & 127;
            int sub = tid >> 7, n = tid & 127;
            const float* X = (p & 1) ? Wn3 : Ws3;
            const float* Y = Wp1 + ((p >> 1) ? 128 * D : 0);
            xr[sub][n] = X[i * D + n];
            __syncthreads();
            float s = 0.f;
            #pragma unroll 8
            for (int k = 0; k < 128; k++) s += xr[sub][k] * Y[k * D + n];
            int dstrow = ((p < 2) ? 512 : 768) + (p & 1) * 128 + i;
            g_wh[dstrow * D + n] = __float2half_rn(s);
        } else {                                  // composed biases
            int half = tid >> 7, n = tid & 127;
            float s = (half == 0) ? bp1[n] : 0.f;
            for (int j = 0; j < 128; j++) s += b3[j] * Wp1[(half * 128 + j) * D + n];
            g_bc[half * D + n] = s;
        }
    }
}

// fused scan: per-block scan + decoupled aggregate lookback + rowptr + cnt reset
__global__ void k_scan_fused() {
    __shared__ int sh[1024];
    __shared__ int red[32];
    int tid = threadIdx.x, blk = blockIdx.x;
    int i = blk * 1024 + tid;
    int v = (i < N_NODES) ? g_cnt[i] : 0;
    sh[tid] = v;
    __syncthreads();
    for (int o = 1; o < 1024; o <<= 1) {
        int t = (tid >= o) ? sh[tid - o] : 0;
        __syncthreads();
        sh[tid] += t;
        __syncthreads();
    }
    int total = sh[1023];
    if (tid == 0) {
        *(volatile int*)&g_bsum[blk] = total;
        __threadfence();
        *(volatile int*)&g_ready[blk] = 1;
    }
    int myv = 0;
    for (int j = tid; j < blk; j += 1024) {
        while (*(volatile int*)&g_ready[j] == 0) {}
        myv += *(volatile int*)&g_bsum[j];
    }
    #pragma unroll
    for (int o = 16; o > 0; o >>= 1) myv += __shfl_xor_sync(0xffffffffu, myv, o);
    if ((tid & 31) == 0) red[tid >> 5] = myv;
    __syncthreads();
    if (tid == 0) {
        int s = 0;
        #pragma unroll
        for (int w = 0; w < 32; w++) s += red[w];
        red[0] = s;
    }
    __syncthreads();
    int pref = red[0];
    if (i < N_NODES) {
        g_rowptr[i] = pref + sh[tid] - v;    // global exclusive
        g_cnt[i] = 0;                        // reset for k_place
    }
    if (blk == NB_SCAN - 1 && tid == 1023) g_rowptr[N_NODES] = pref + total;
}

__global__ void k_place(const int* __restrict__ src, const int* __restrict__ dst) {
    int e = blockIdx.x * blockDim.x + threadIdx.x;
    if (e < N_EDGES) {
        int d = dst[e];
        int slot = g_rowptr[d] + atomicAdd(&g_cnt[d], 1);
        g_csr[slot] = src[e];
    }
}

// ---------------- mean aggregation: half-warp/node, unrolled x2 ------------
__global__ void k_agg(const __half* __restrict__ xin) {
    int g = blockIdx.x * blockDim.x + threadIdx.x;
    int node = g >> 4, lane16 = g & 15;
    if (node >= N_NODES) return;
    int beg = g_rowptr[node], end = g_rowptr[node + 1];
    float a0 = 0.f, a1 = 0.f, a2 = 0.f, a3 = 0.f;
    float a4 = 0.f, a5 = 0.f, a6 = 0.f, a7 = 0.f;
    int e = beg;
    for (; e + 1 < end; e += 2) {
        int s0 = g_csr[e], s1 = g_csr[e + 1];
        const uint4 v0 = *(const uint4*)&xin[(size_t)s0 * D + lane16 * 8];
        const uint4 v1 = *(const uint4*)&xin[(size_t)s1 * D + lane16 * 8];
        float2 f;
        f = __half22float2(*(__half2*)&v0.x); a0 += f.x; a1 += f.y;
        f = __half22float2(*(__half2*)&v0.y); a2 += f.x; a3 += f.y;
        f = __half22float2(*(__half2*)&v0.z); a4 += f.x; a5 += f.y;
        f = __half22float2(*(__half2*)&v0.w); a6 += f.x; a7 += f.y;
        f = __half22float2(*(__half2*)&v1.x); a0 += f.x; a1 += f.y;
        f = __half22float2(*(__half2*)&v1.y); a2 += f.x; a3 += f.y;
        f = __half22float2(*(__half2*)&v1.z); a4 += f.x; a5 += f.y;
        f = __half22float2(*(__half2*)&v1.w); a6 += f.x; a7 += f.y;
    }
    if (e < end) {
        const uint4 v = *(const uint4*)&xin[(size_t)g_csr[e] * D + lane16 * 8];
        float2 f;
        f = __half22float2(*(__half2*)&v.x); a0 += f.x; a1 += f.y;
        f = __half22float2(*(__half2*)&v.y); a2 += f.x; a3 += f.y;
        f = __half22float2(*(__half2*)&v.z); a4 += f.x; a5 += f.y;
        f = __half22float2(*(__half2*)&v.w); a6 += f.x; a7 += f.y;
    }
    int deg = end - beg;
    float inv = 1.0f / (float)(deg > 1 ? deg : 1);
    uint4 outv;
    *(__half2*)&outv.x = __floats2half2_rn(a0 * inv, a1 * inv);
    *(__half2*)&outv.y = __floats2half2_rn(a2 * inv, a3 * inv);
    *(__half2*)&outv.z = __floats2half2_rn(a4 * inv, a5 * inv);
    *(__half2*)&outv.w = __floats2half2_rn(a6 * inv, a7 * inv);
    *(uint4*)&g_m[(size_t)node * D + lane16 * 8] = outv;
}

// ---------------- tensor-core GEMM (fp16, 1-term, 3-stage, 2 CTA/SM) -------
__device__ __forceinline__ void ldsm4(uint32_t& r0, uint32_t& r1, uint32_t& r2,
                                      uint32_t& r3, uint32_t addr) {
    asm volatile("ldmatrix.sync.aligned.m8n8.x4.shared.b16 {%0,%1,%2,%3}, [%4];"
                 : "=r"(r0), "=r"(r1), "=r"(r2), "=r"(r3) : "r"(addr));
}
__device__ __forceinline__ void ldsm4t(uint32_t& r0, uint32_t& r1, uint32_t& r2,
                                       uint32_t& r3, uint32_t addr) {
    asm volatile("ldmatrix.sync.aligned.m8n8.x4.trans.shared.b16 {%0,%1,%2,%3}, [%4];"
                 : "=r"(r0), "=r"(r1), "=r"(r2), "=r"(r3) : "r"(addr));
}
__device__ __forceinline__ void mma_fp16(float* c, const uint32_t* a, const uint32_t* b) {
    asm volatile(
        "mma.sync.aligned.m16n8k16.row.col.f32.f16.f16.f32 "
        "{%0,%1,%2,%3},{%4,%5,%6,%7},{%8,%9},{%0,%1,%2,%3};"
        : "+f"(c[0]), "+f"(c[1]), "+f"(c[2]), "+f"(c[3])
        : "r"(a[0]), "r"(a[1]), "r"(a[2]), "r"(a[3]), "r"(b[0]), "r"(b[1]));
}
__device__ __forceinline__ void cp16(uint32_t s, const void* g, bool p) {
    asm volatile("cp.async.cg.shared.global [%0], [%1], 16, %2;"
                 :: "r"(s), "l"(g), "r"(p ? 16 : 0));
}

#define A_STRIDE 80u
#define B_STRIDE 272u
#define A_BYTES (128u * A_STRIDE)            // 10240
#define B_BYTES (32u * B_STRIDE)             // 8704
#define STAGE (A_BYTES + B_BYTES)            // 18944
#define GEMM_SMEM (3 * STAGE)                // 56832 -> 2 CTAs/SM

// out[M,128] = (A1|A2)[M,K=256] @ W[K,128] + bias ; fp16.
// If pred (gridDim.y==2): y==1 selects W+256 rows, bias+128, out=outB.
__global__ __launch_bounds__(256, 2) void k_gemm_tc(
    const __half* __restrict__ A1, const __half* __restrict__ A2,
    const __half* __restrict__ Wh,
    const float* __restrict__ bias,
    __half* __restrict__ outA, __half* __restrict__ outB,
    int M, int K)
{
    extern __shared__ char smdyn[];
    uint32_t base = (uint32_t)__cvta_generic_to_shared(smdyn);

    __half* outp = outA;
    if (outB && blockIdx.y == 1) {
        Wh += 256 * D; bias += 128; outp = outB;
    }

    int tid = threadIdx.x;
    int wid = tid >> 5, lane = tid & 31;
    int warp_m = (wid >> 2) * 64;
    int warp_n = (wid & 3) * 32;
    int m0 = blockIdx.x * 128;
    int nch = K / 32;

    float c[4][4][4];
    #pragma unroll
    for (int i = 0; i < 4; i++)
        #pragma unroll
        for (int j = 0; j < 4; j++)
            #pragma unroll
            for (int q = 0; q < 4; q++) c[i][j][q] = 0.f;

    auto load_chunk = [&](int ch) {
        uint32_t st = base + (uint32_t)(ch % 3) * STAGE;
        int kb = ch * 32;
        const __half* A = (kb < 128) ? A1 : A2;
        int ac = kb & 127;
        #pragma unroll
        for (int l = tid; l < 512; l += 256) {      // A: 128 rows x 4 segs(16B)
            int r = l >> 2, seg = l & 3;
            uint32_t so = (uint32_t)r * A_STRIDE + (uint32_t)seg * 16u;
            bool p = (m0 + r) < M;
            int rr = p ? (m0 + r) : 0;
            cp16(st + so, A + (size_t)rr * D + ac + seg * 8, p);
        }
        #pragma unroll
        for (int l = tid; l < 512; l += 256) {      // B: 32 rows x 16 segs
            int r = l >> 4, seg = l & 15;
            uint32_t so = (uint32_t)r * B_STRIDE + (uint32_t)seg * 16u;
            cp16(st + A_BYTES + so, Wh + (size_t)(kb + r) * D + seg * 8, true);
        }
        asm volatile("cp.async.commit_group;" ::: "memory");
    };

    load_chunk(0);
    load_chunk(1);

    int lr = (lane & 7) + 8 * ((lane >> 3) & 1);
    int lc = 8 * (lane >> 4);

    for (int ch = 0; ch < nch; ch++) {
        if (ch + 1 < nch) {
            asm volatile("cp.async.wait_group 1;" ::: "memory");
        } else {
            asm volatile("cp.async.wait_group 0;" ::: "memory");
        }
        __syncthreads();     // single barrier: orders stage reuse + visibility
        if (ch + 2 < nch) load_chunk(ch + 2);

        uint32_t st  = base + (uint32_t)(ch % 3) * STAGE;
        uint32_t a_b = st;
        uint32_t b_b = st + A_BYTES;

        #pragma unroll
        for (int ks = 0; ks < 2; ks++) {
            int k0 = ks * 16;
            uint32_t a[4][4];
            #pragma unroll
            for (int mi = 0; mi < 4; mi++) {
                uint32_t ro = (uint32_t)(warp_m + mi * 16 + lr) * A_STRIDE
                            + (uint32_t)(k0 + lc) * 2u;
                ldsm4(a[mi][0], a[mi][1], a[mi][2], a[mi][3], a_b + ro);
            }
            uint32_t b[4][2];
            #pragma unroll
            for (int njp = 0; njp < 2; njp++) {
                uint32_t ro = (uint32_t)(k0 + lr) * B_STRIDE
                            + (uint32_t)(warp_n + njp * 16 + lc) * 2u;
                uint32_t r0, r1, r2, r3;
                ldsm4t(r0, r1, r2, r3, b_b + ro);
                b[2 * njp][0] = r0;     b[2 * njp][1] = r1;
                b[2 * njp + 1][0] = r2; b[2 * njp + 1][1] = r3;
            }
            #pragma unroll
            for (int mi = 0; mi < 4; mi++)
                #pragma unroll
                for (int nj = 0; nj < 4; nj++)
                    mma_fp16(c[mi][nj], a[mi], b[nj]);
        }
    }

    // epilogue: fp16 output
    #pragma unroll
    for (int mi = 0; mi < 4; mi++) {
        #pragma unroll
        for (int nj = 0; nj < 4; nj++) {
            int row0 = m0 + warp_m + mi * 16 + (lane >> 2);
            int col  = warp_n + nj * 8 + (lane & 3) * 2;
            float b0 = bias ? bias[col] : 0.f;
            float b1 = bias ? bias[col + 1] : 0.f;
            #pragma unroll
            for (int h = 0; h < 2; h++) {
                int row = row0 + 8 * h;
                if (row < M) {
                    float v0 = c[mi][nj][2 * h]     + b0;
                    float v1 = c[mi][nj][2 * h + 1] + b1;
                    *(__half2*)&outp[(size_t)row * D + col] =
                        __floats2half2_rn(v0, v1);
                }
            }
        }
    }
}

// ---------------- edge scoring + state reset (16 lanes/edge) ----------------
__global__ void k_edge(const int* __restrict__ s1, const int* __restrict__ d1,
                       const int* __restrict__ s2, const int* __restrict__ d2,
                       const float* __restrict__ Wp2, const float* __restrict__ bp2,
                       float* __restrict__ out)
{
    int g = blockIdx.x * blockDim.x + threadIdx.x;
    // restore launch-entry invariant (g_cnt == 0, g_ready == 0)
    if (g < N_NODES) g_cnt[g] = 0;
    if (g < NB_SCAN) g_ready[g] = 0;
    int e = g >> 4, lane16 = g & 15;
    if (e >= 2 * N_EDGES) return;
    int ss, dd;
    if (e < N_EDGES) { ss = s1[e]; dd = d1[e]; }
    else             { ss = s2[e - N_EDGES]; dd = d2[e - N_EDGES]; }

    uint4 av = *(const uint4*)&g_pa16[(size_t)ss * D + lane16 * 8];
    uint4 bv = *(const uint4*)&g_pb16[(size_t)dd * D + lane16 * 8];
    float4 w0 = *(const float4*)&Wp2[lane16 * 8];
    float4 w1 = *(const float4*)&Wp2[lane16 * 8 + 4];

    float2 a0 = __half22float2(*(__half2*)&av.x);
    float2 a1 = __half22float2(*(__half2*)&av.y);
    float2 a2 = __half22float2(*(__half2*)&av.z);
    float2 a3 = __half22float2(*(__half2*)&av.w);
    float2 b0 = __half22float2(*(__half2*)&bv.x);
    float2 b1 = __half22float2(*(__half2*)&bv.y);
    float2 b2 = __half22float2(*(__half2*)&bv.z);
    float2 b3 = __half22float2(*(__half2*)&bv.w);

    float p = fmaxf(a0.x + b0.x, 0.f) * w0.x
            + fmaxf(a0.y + b0.y, 0.f) * w0.y
            + fmaxf(a1.x + b1.x, 0.f) * w0.z
            + fmaxf(a1.y + b1.y, 0.f) * w0.w
            + fmaxf(a2.x + b2.x, 0.f) * w1.x
            + fmaxf(a2.y + b2.y, 0.f) * w1.y
            + fmaxf(a3.x + b3.x, 0.f) * w1.z
            + fmaxf(a3.y + b3.y, 0.f) * w1.w;
    #pragma unroll
    for (int o = 8; o > 0; o >>= 1) p += __shfl_xor_sync(0xffffffffu, p, o);
    if (lane16 == 0) out[e] = p + bp2[0];
}

// ---------------- launch ----------------------------------------------------
extern "C" void kernel_launch(void* const* d_in, const int* in_sizes, int n_in,
                              void* d_out, int out_size)
{
    const float* x    = (const float*)d_in[0];
    const int*   src  = (const int*)d_in[1];
    const int*   dst  = (const int*)d_in[2];
    const int*   nsrc = (const int*)d_in[3];
    const int*   ndst = (const int*)d_in[4];
    const float* Ws1 = (const float*)d_in[5],  *Wn1 = (const float*)d_in[6],  *b1 = (const float*)d_in[7];
    const float* Ws2 = (const float*)d_in[8],  *Wn2 = (const float*)d_in[9],  *b2 = (const float*)d_in[10];
    const float* Ws3 = (const float*)d_in[11], *Wn3 = (const float*)d_in[12], *b3 = (const float*)d_in[13];
    const float* Wp1 = (const float*)d_in[14], *bp1 = (const float*)d_in[15];
    const float* Wp2 = (const float*)d_in[16], *bp2 = (const float*)d_in[17];
    float* out = (float*)d_out;

    __half *p_pa16, *p_pb16, *p_x, *p_m, *p_h1, *p_h2, *p_wh;
    float* p_bc;
    cudaGetSymbolAddress((void**)&p_pa16, g_pa16);
    cudaGetSymbolAddress((void**)&p_pb16, g_pb16);
    cudaGetSymbolAddress((void**)&p_x, g_x);
    cudaGetSymbolAddress((void**)&p_m, g_m);
    cudaGetSymbolAddress((void**)&p_h1, g_h1);
    cudaGetSymbolAddress((void**)&p_h2, g_h2);
    cudaGetSymbolAddress((void**)&p_wh, g_wh);
    cudaGetSymbolAddress((void**)&p_bc, g_bc);

    cudaFuncSetAttribute(k_gemm_tc, cudaFuncAttributeMaxDynamicSharedMemorySize,
                         GEMM_SMEM);

    // --- fused prologue: x-cvt + hist + weight prep (independent work) ---
    k_prep<<<CVT_BLOCKS + HIST_BLOCKS + WPREP_BLOCKS, 256>>>(
        x, p_x, dst, Ws1, Wn1, Ws2, Wn2, Ws3, Wn3, Wp1, b3, bp1);
    // --- CSR scan + place ---
    k_scan_fused<<<NB_SCAN, 1024>>>();
    k_place<<<(N_EDGES + 255) / 256, 256>>>(src, dst);

    const int aggBlocks  = (N_NODES * 16 + 255) / 256;
    const int gemmBlocks = (N_NODES + 127) / 128;

    // --- layer 1 ---
    k_agg<<<aggBlocks, 256>>>(p_x);
    k_gemm_tc<<<gemmBlocks, 256, GEMM_SMEM>>>(p_x, p_m, p_wh, b1,
                                              p_h1, nullptr, N_NODES, 256);
    // --- layer 2 ---
    k_agg<<<aggBlocks, 256>>>(p_h1);
    k_gemm_tc<<<gemmBlocks, 256, GEMM_SMEM>>>(p_h1, p_m, p_wh + 256 * D, b2,
                                              p_h2, nullptr, N_NODES, 256);
    // --- layer 3 + predictor (fused via composed weights; gridDim.y=2) ---
    k_agg<<<aggBlocks, 256>>>(p_h2);
    k_gemm_tc<<<dim3(gemmBlocks, 2), 256, GEMM_SMEM>>>(
                                              p_h2, p_m, p_wh + 512 * D, p_bc,
                                              p_pa16, p_pb16, N_NODES, 256);

    // --- edge scores (+ restores cnt/ready invariant) ---
    k_edge<<<(2 * N_EDGES * 16 + 255) / 256, 256>>>(src, dst, nsrc, ndst, Wp2, bp2, out);
}

// round 14
// speedup vs baseline: 2.0168x; 1.0129x over previous
#include <cuda_runtime.h>
#include <cuda_bf16.h>
#include <cuda_fp16.h>
#include <cstdint>

#define N_NODES 100000
#define N_EDGES 640000
#define D 128
#define NB_SCAN ((N_NODES + 1023) / 1024)    // 98

#define CVT_BLOCKS 12500                     // N_NODES*D/4 / 256
#define HIST_BLOCKS 625                      // N_EDGES / (256*4)
#define WPREP_BLOCKS 513

// ---------------- scratch (device globals: zero at module load) ------------
__device__ __align__(16) __half g_pa16[N_NODES * D];
__device__ __align__(16) __half g_pb16[N_NODES * D];
// node tensors: fp16 [N][128]
__device__ __align__(16) __half g_x[N_NODES * D];
__device__ __align__(16) __half g_m[N_NODES * D];
__device__ __align__(16) __half g_h1[N_NODES * D];
__device__ __align__(16) __half g_h2[N_NODES * D];
// packed weights [K][N] fp16:
// rows [Ws1|Wn1 (0-255) | Ws2|Wn2 (256-511) | comp_pa (512-767) | comp_pb (768-1023)]
__device__ __align__(16) __half g_wh[1024 * D];
__device__ float g_bc[2 * D];                // composed predictor biases
// CSR  (INVARIANT: g_cnt == 0 and g_ready == 0 at kernel_launch entry;
//       k_edge restores this at the end of every launch)
__device__ int g_cnt[N_NODES];
__device__ int g_rowptr[N_NODES + 1];
__device__ int g_csr[N_EDGES];
__device__ int g_bsum[NB_SCAN];
__device__ int g_ready[NB_SCAN];

// ---------------- fused prologue: x-cvt + dst-hist + weight prep -----------
__global__ void k_prep(const float* __restrict__ x, __half* __restrict__ xo,
                       const int* __restrict__ dst,
                       const float* __restrict__ Ws1, const float* __restrict__ Wn1,
                       const float* __restrict__ Ws2, const float* __restrict__ Wn2,
                       const float* __restrict__ Ws3, const float* __restrict__ Wn3,
                       const float* __restrict__ Wp1, const float* __restrict__ b3,
                       const float* __restrict__ bp1) {
    int blk = blockIdx.x, tid = threadIdx.x;
    if (blk < CVT_BLOCKS) {                       // ---- x fp32 -> fp16
        int i = blk * 256 + tid;                  // < 3.2M exactly
        float4 v = ((const float4*)x)[i];
        __half2* p = (__half2*)&xo[i * 4];
        p[0] = __floats2half2_rn(v.x, v.y);
        p[1] = __floats2half2_rn(v.z, v.w);
    } else if (blk < CVT_BLOCKS + HIST_BLOCKS) {  // ---- degree histogram x4
        int e4 = (blk - CVT_BLOCKS) * 256 + tid;  // < 160000 exactly
        int4 d4 = ((const int4*)dst)[e4];
        atomicAdd(&g_cnt[d4.x], 1);
        atomicAdd(&g_cnt[d4.y], 1);
        atomicAdd(&g_cnt[d4.z], 1);
        atomicAdd(&g_cnt[d4.w], 1);
    } else {                                      // ---- weight prep
        int wb = blk - CVT_BLOCKS - HIST_BLOCKS;  // 0..512
        if (wb < 256) {                           // layer 1/2 weights
            int i = wb * 256 + tid;
            int row = i >> 7, col = i & 127;
            const float* s; int lr;
            if      (row < 128)  { s = Ws1; lr = row; }
            else if (row < 256)  { s = Wn1; lr = row - 128; }
            else if (row < 384)  { s = Ws2; lr = row - 256; }
            else                 { s = Wn2; lr = row - 384; }
            g_wh[i] = __float2half_rn(s[lr * D + col]);
        } else if (wb < 512) {                    // composed predictor weights
            __shared__ float xr[2][128];
            int idx = (wb - 256) * 2 + (tid >> 7);
            int p = idx >> 7, i = idx & 127;
            int sub = tid >> 7, n = tid & 127;
            const float* X = (p & 1) ? Wn3 : Ws3;
            const float* Y = Wp1 + ((p >> 1) ? 128 * D : 0);
            xr[sub][n] = X[i * D + n];
            __syncthreads();
            float s = 0.f;
            #pragma unroll 8
            for (int k = 0; k < 128; k++) s += xr[sub][k] * Y[k * D + n];
            int dstrow = ((p < 2) ? 512 : 768) + (p & 1) * 128 + i;
            g_wh[dstrow * D + n] = __float2half_rn(s);
        } else {                                  // composed biases
            int half = tid >> 7, n = tid & 127;
            float s = (half == 0) ? bp1[n] : 0.f;
            for (int j = 0; j < 128; j++) s += b3[j] * Wp1[(half * 128 + j) * D + n];
            g_bc[half * D + n] = s;
        }
    }
}

// fused scan: per-block scan + decoupled aggregate lookback + rowptr + cnt reset
__global__ void k_scan_fused() {
    __shared__ int sh[1024];
    __shared__ int red[32];
    int tid = threadIdx.x, blk = blockIdx.x;
    int i = blk * 1024 + tid;
    int v = (i < N_NODES) ? g_cnt[i] : 0;
    sh[tid] = v;
    __syncthreads();
    for (int o = 1; o < 1024; o <<= 1) {
        int t = (tid >= o) ? sh[tid - o] : 0;
        __syncthreads();
        sh[tid] += t;
        __syncthreads();
    }
    int total = sh[1023];
    if (tid == 0) {
        *(volatile int*)&g_bsum[blk] = total;
        __threadfence();
        *(volatile int*)&g_ready[blk] = 1;
    }
    int myv = 0;
    for (int j = tid; j < blk; j += 1024) {
        while (*(volatile int*)&g_ready[j] == 0) {}
        myv += *(volatile int*)&g_bsum[j];
    }
    #pragma unroll
    for (int o = 16; o > 0; o >>= 1) myv += __shfl_xor_sync(0xffffffffu, myv, o);
    if ((tid & 31) == 0) red[tid >> 5] = myv;
    __syncthreads();
    if (tid == 0) {
        int s = 0;
        #pragma unroll
        for (int w = 0; w < 32; w++) s += red[w];
        red[0] = s;
    }
    __syncthreads();
    int pref = red[0];
    if (i < N_NODES) {
        g_rowptr[i] = pref + sh[tid] - v;    // global exclusive
        g_cnt[i] = 0;                        // reset for k_place
    }
    if (blk == NB_SCAN - 1 && tid == 1023) g_rowptr[N_NODES] = pref + total;
}

// 4 edges per thread for memory-level parallelism
__global__ void k_place(const int* __restrict__ src, const int* __restrict__ dst) {
    int e4 = blockIdx.x * blockDim.x + threadIdx.x;
    if (e4 >= N_EDGES / 4) return;
    int4 d4 = ((const int4*)dst)[e4];
    int4 s4 = ((const int4*)src)[e4];
    int p0 = g_rowptr[d4.x] + atomicAdd(&g_cnt[d4.x], 1);
    int p1 = g_rowptr[d4.y] + atomicAdd(&g_cnt[d4.y], 1);
    int p2 = g_rowptr[d4.z] + atomicAdd(&g_cnt[d4.z], 1);
    int p3 = g_rowptr[d4.w] + atomicAdd(&g_cnt[d4.w], 1);
    g_csr[p0] = s4.x; g_csr[p1] = s4.y; g_csr[p2] = s4.z; g_csr[p3] = s4.w;
}

// ---------------- mean aggregation: half-warp/node, fp16 pairwise pre-add --
__global__ void k_agg(const __half* __restrict__ xin) {
    int g = blockIdx.x * blockDim.x + threadIdx.x;
    int node = g >> 4, lane16 = g & 15;
    if (node >= N_NODES) return;
    int beg = g_rowptr[node], end = g_rowptr[node + 1];
    float a0 = 0.f, a1 = 0.f, a2 = 0.f, a3 = 0.f;
    float a4 = 0.f, a5 = 0.f, a6 = 0.f, a7 = 0.f;
    int e = beg;
    for (; e + 1 < end; e += 2) {
        int s0 = g_csr[e], s1 = g_csr[e + 1];
        const uint4 v0 = *(const uint4*)&xin[(size_t)s0 * D + lane16 * 8];
        const uint4 v1 = *(const uint4*)&xin[(size_t)s1 * D + lane16 * 8];
        // pairwise fp16 add (one extra 2^-11 rounding per pair: negligible)
        __half2 h0 = __hadd2(*(__half2*)&v0.x, *(__half2*)&v1.x);
        __half2 h1 = __hadd2(*(__half2*)&v0.y, *(__half2*)&v1.y);
        __half2 h2 = __hadd2(*(__half2*)&v0.z, *(__half2*)&v1.z);
        __half2 h3 = __hadd2(*(__half2*)&v0.w, *(__half2*)&v1.w);
        float2 f;
        f = __half22float2(h0); a0 += f.x; a1 += f.y;
        f = __half22float2(h1); a2 += f.x; a3 += f.y;
        f = __half22float2(h2); a4 += f.x; a5 += f.y;
        f = __half22float2(h3); a6 += f.x; a7 += f.y;
    }
    if (e < end) {
        const uint4 v = *(const uint4*)&xin[(size_t)g_csr[e] * D + lane16 * 8];
        float2 f;
        f = __half22float2(*(__half2*)&v.x); a0 += f.x; a1 += f.y;
        f = __half22float2(*(__half2*)&v.y); a2 += f.x; a3 += f.y;
        f = __half22float2(*(__half2*)&v.z); a4 += f.x; a5 += f.y;
        f = __half22float2(*(__half2*)&v.w); a6 += f.x; a7 += f.y;
    }
    int deg = end - beg;
    float inv = 1.0f / (float)(deg > 1 ? deg : 1);
    uint4 outv;
    *(__half2*)&outv.x = __floats2half2_rn(a0 * inv, a1 * inv);
    *(__half2*)&outv.y = __floats2half2_rn(a2 * inv, a3 * inv);
    *(__half2*)&outv.z = __floats2half2_rn(a4 * inv, a5 * inv);
    *(__half2*)&outv.w = __floats2half2_rn(a6 * inv, a7 * inv);
    *(uint4*)&g_m[(size_t)node * D + lane16 * 8] = outv;
}

// ---------------- tensor-core GEMM (fp16, 1-term, 3-stage, 2 CTA/SM) -------
__device__ __forceinline__ void ldsm4(uint32_t& r0, uint32_t& r1, uint32_t& r2,
                                      uint32_t& r3, uint32_t addr) {
    asm volatile("ldmatrix.sync.aligned.m8n8.x4.shared.b16 {%0,%1,%2,%3}, [%4];"
                 : "=r"(r0), "=r"(r1), "=r"(r2), "=r"(r3) : "r"(addr));
}
__device__ __forceinline__ void ldsm4t(uint32_t& r0, uint32_t& r1, uint32_t& r2,
                                       uint32_t& r3, uint32_t addr) {
    asm volatile("ldmatrix.sync.aligned.m8n8.x4.trans.shared.b16 {%0,%1,%2,%3}, [%4];"
                 : "=r"(r0), "=r"(r1), "=r"(r2), "=r"(r3) : "r"(addr));
}
__device__ __forceinline__ void mma_fp16(float* c, const uint32_t* a, const uint32_t* b) {
    asm volatile(
        "mma.sync.aligned.m16n8k16.row.col.f32.f16.f16.f32 "
        "{%0,%1,%2,%3},{%4,%5,%6,%7},{%8,%9},{%0,%1,%2,%3};"
        : "+f"(c[0]), "+f"(c[1]), "+f"(c[2]), "+f"(c[3])
        : "r"(a[0]), "r"(a[1]), "r"(a[2]), "r"(a[3]), "r"(b[0]), "r"(b[1]));
}
__device__ __forceinline__ void cp16(uint32_t s, const void* g, bool p) {
    asm volatile("cp.async.cg.shared.global [%0], [%1], 16, %2;"
                 :: "r"(s), "l"(g), "r"(p ? 16 : 0));
}

#define A_STRIDE 80u
#define B_STRIDE 272u
#define A_BYTES (128u * A_STRIDE)            // 10240
#define B_BYTES (32u * B_STRIDE)             // 8704
#define STAGE (A_BYTES + B_BYTES)            // 18944
#define GEMM_SMEM (3 * STAGE)                // 56832 -> 2 CTAs/SM

// out[M,128] = (A1|A2)[M,K=256] @ W[K,128] + bias ; fp16.
// If pred (gridDim.y==2): y==1 selects W+256 rows, bias+128, out=outB.
__global__ __launch_bounds__(256, 2) void k_gemm_tc(
    const __half* __restrict__ A1, const __half* __restrict__ A2,
    const __half* __restrict__ Wh,
    const float* __restrict__ bias,
    __half* __restrict__ outA, __half* __restrict__ outB,
    int M, int K)
{
    extern __shared__ char smdyn[];
    uint32_t base = (uint32_t)__cvta_generic_to_shared(smdyn);

    __half* outp = outA;
    if (outB && blockIdx.y == 1) {
        Wh += 256 * D; bias += 128; outp = outB;
    }

    int tid = threadIdx.x;
    int wid = tid >> 5, lane = tid & 31;
    int warp_m = (wid >> 2) * 64;
    int warp_n = (wid & 3) * 32;
    int m0 = blockIdx.x * 128;
    int nch = K / 32;

    float c[4][4][4];
    #pragma unroll
    for (int i = 0; i < 4; i++)
        #pragma unroll
        for (int j = 0; j < 4; j++)
            #pragma unroll
            for (int q = 0; q < 4; q++) c[i][j][q] = 0.f;

    auto load_chunk = [&](int ch) {
        uint32_t st = base + (uint32_t)(ch % 3) * STAGE;
        int kb = ch * 32;
        const __half* A = (kb < 128) ? A1 : A2;
        int ac = kb & 127;
        #pragma unroll
        for (int l = tid; l < 512; l += 256) {      // A: 128 rows x 4 segs(16B)
            int r = l >> 2, seg = l & 3;
            uint32_t so = (uint32_t)r * A_STRIDE + (uint32_t)seg * 16u;
            bool p = (m0 + r) < M;
            int rr = p ? (m0 + r) : 0;
            cp16(st + so, A + (size_t)rr * D + ac + seg * 8, p);
        }
        #pragma unroll
        for (int l = tid; l < 512; l += 256) {      // B: 32 rows x 16 segs
            int r = l >> 4, seg = l & 15;
            uint32_t so = (uint32_t)r * B_STRIDE + (uint32_t)seg * 16u;
            cp16(st + A_BYTES + so, Wh + (size_t)(kb + r) * D + seg * 8, true);
        }
        asm volatile("cp.async.commit_group;" ::: "memory");
    };

    load_chunk(0);
    load_chunk(1);

    int lr = (lane & 7) + 8 * ((lane >> 3) & 1);
    int lc = 8 * (lane >> 4);

    for (int ch = 0; ch < nch; ch++) {
        if (ch + 1 < nch) {
            asm volatile("cp.async.wait_group 1;" ::: "memory");
        } else {
            asm volatile("cp.async.wait_group 0;" ::: "memory");
        }
        __syncthreads();     // single barrier: orders stage reuse + visibility
        if (ch + 2 < nch) load_chunk(ch + 2);

        uint32_t st  = base + (uint32_t)(ch % 3) * STAGE;
        uint32_t a_b = st;
        uint32_t b_b = st + A_BYTES;

        #pragma unroll
        for (int ks = 0; ks < 2; ks++) {
            int k0 = ks * 16;
            uint32_t a[4][4];
            #pragma unroll
            for (int mi = 0; mi < 4; mi++) {
                uint32_t ro = (uint32_t)(warp_m + mi * 16 + lr) * A_STRIDE
                            + (uint32_t)(k0 + lc) * 2u;
                ldsm4(a[mi][0], a[mi][1], a[mi][2], a[mi][3], a_b + ro);
            }
            uint32_t b[4][2];
            #pragma unroll
            for (int njp = 0; njp < 2; njp++) {
                uint32_t ro = (uint32_t)(k0 + lr) * B_STRIDE
                            + (uint32_t)(warp_n + njp * 16 + lc) * 2u;
                uint32_t r0, r1, r2, r3;
                ldsm4t(r0, r1, r2, r3, b_b + ro);
                b[2 * njp][0] = r0;     b[2 * njp][1] = r1;
                b[2 * njp + 1][0] = r2; b[2 * njp + 1][1] = r3;
            }
            #pragma unroll
            for (int mi = 0; mi < 4; mi++)
                #pragma unroll
                for (int nj = 0; nj < 4; nj++)
                    mma_fp16(c[mi][nj], a[mi], b[nj]);
        }
    }

    // epilogue: fp16 output
    #pragma unroll
    for (int mi = 0; mi < 4; mi++) {
        #pragma unroll
        for (int nj = 0; nj < 4; nj++) {
            int row0 = m0 + warp_m + mi * 16 + (lane >> 2);
            int col  = warp_n + nj * 8 + (lane & 3) * 2;
            float b0 = bias ? bias[col] : 0.f;
            float b1 = bias ? bias[col + 1] : 0.f;
            #pragma unroll
            for (int h = 0; h < 2; h++) {
                int row = row0 + 8 * h;
                if (row < M) {
                    float v0 = c[mi][nj][2 * h]     + b0;
                    float v1 = c[mi][nj][2 * h + 1] + b1;
                    *(__half2*)&outp[(size_t)row * D + col] =
                        __floats2half2_rn(v0, v1);
                }
            }
        }
    }
}

// ---------------- edge scoring + state reset (16 lanes/edge) ----------------
__global__ void k_edge(const int* __restrict__ s1, const int* __restrict__ d1,
                       const int* __restrict__ s2, const int* __restrict__ d2,
                       const float* __restrict__ Wp2, const float* __restrict__ bp2,
                       float* __restrict__ out)
{
    int g = blockIdx.x * blockDim.x + threadIdx.x;
    // restore launch-entry invariant (g_cnt == 0, g_ready == 0)
    if (g < N_NODES) g_cnt[g] = 0;
    if (g < NB_SCAN) g_ready[g] = 0;
    int e = g >> 4, lane16 = g & 15;
    if (e >= 2 * N_EDGES) return;
    int ss, dd;
    if (e < N_EDGES) { ss = s1[e]; dd = d1[e]; }
    else             { ss = s2[e - N_EDGES]; dd = d2[e - N_EDGES]; }

    uint4 av = *(const uint4*)&g_pa16[(size_t)ss * D + lane16 * 8];
    uint4 bv = *(const uint4*)&g_pb16[(size_t)dd * D + lane16 * 8];
    float4 w0 = *(const float4*)&Wp2[lane16 * 8];
    float4 w1 = *(const float4*)&Wp2[lane16 * 8 + 4];

    float2 a0 = __half22float2(*(__half2*)&av.x);
    float2 a1 = __half22float2(*(__half2*)&av.y);
    float2 a2 = __half22float2(*(__half2*)&av.z);
    float2 a3 = __half22float2(*(__half2*)&av.w);
    float2 b0 = __half22float2(*(__half2*)&bv.x);
    float2 b1 = __half22float2(*(__half2*)&bv.y);
    float2 b2 = __half22float2(*(__half2*)&bv.z);
    float2 b3 = __half22float2(*(__half2*)&bv.w);

    float p = fmaxf(a0.x + b0.x, 0.f) * w0.x
            + fmaxf(a0.y + b0.y, 0.f) * w0.y
            + fmaxf(a1.x + b1.x, 0.f) * w0.z
            + fmaxf(a1.y + b1.y, 0.f) * w0.w
            + fmaxf(a2.x + b2.x, 0.f) * w1.x
            + fmaxf(a2.y + b2.y, 0.f) * w1.y
            + fmaxf(a3.x + b3.x, 0.f) * w1.z
            + fmaxf(a3.y + b3.y, 0.f) * w1.w;
    #pragma unroll
    for (int o = 8; o > 0; o >>= 1) p += __shfl_xor_sync(0xffffffffu, p, o);
    if (lane16 == 0) out[e] = p + bp2[0];
}

// ---------------- launch ----------------------------------------------------
extern "C" void kernel_launch(void* const* d_in, const int* in_sizes, int n_in,
                              void* d_out, int out_size)
{
    const float* x    = (const float*)d_in[0];
    const int*   src  = (const int*)d_in[1];
    const int*   dst  = (const int*)d_in[2];
    const int*   nsrc = (const int*)d_in[3];
    const int*   ndst = (const int*)d_in[4];
    const float* Ws1 = (const float*)d_in[5],  *Wn1 = (const float*)d_in[6],  *b1 = (const float*)d_in[7];
    const float* Ws2 = (const float*)d_in[8],  *Wn2 = (const float*)d_in[9],  *b2 = (const float*)d_in[10];
    const float* Ws3 = (const float*)d_in[11], *Wn3 = (const float*)d_in[12], *b3 = (const float*)d_in[13];
    const float* Wp1 = (const float*)d_in[14], *bp1 = (const float*)d_in[15];
    const float* Wp2 = (const float*)d_in[16], *bp2 = (const float*)d_in[17];
    float* out = (float*)d_out;

    __half *p_pa16, *p_pb16, *p_x, *p_m, *p_h1, *p_h2, *p_wh;
    float* p_bc;
    cudaGetSymbolAddress((void**)&p_pa16, g_pa16);
    cudaGetSymbolAddress((void**)&p_pb16, g_pb16);
    cudaGetSymbolAddress((void**)&p_x, g_x);
    cudaGetSymbolAddress((void**)&p_m, g_m);
    cudaGetSymbolAddress((void**)&p_h1, g_h1);
    cudaGetSymbolAddress((void**)&p_h2, g_h2);
    cudaGetSymbolAddress((void**)&p_wh, g_wh);
    cudaGetSymbolAddress((void**)&p_bc, g_bc);

    cudaFuncSetAttribute(k_gemm_tc, cudaFuncAttributeMaxDynamicSharedMemorySize,
                         GEMM_SMEM);

    // --- fused prologue: x-cvt + hist + weight prep (independent work) ---
    k_prep<<<CVT_BLOCKS + HIST_BLOCKS + WPREP_BLOCKS, 256>>>(
        x, p_x, dst, Ws1, Wn1, Ws2, Wn2, Ws3, Wn3, Wp1, b3, bp1);
    // --- CSR scan + place ---
    k_scan_fused<<<NB_SCAN, 1024>>>();
    k_place<<<(N_EDGES / 4 + 255) / 256, 256>>>(src, dst);

    const int aggBlocks  = (N_NODES * 16 + 255) / 256;
    const int gemmBlocks = (N_NODES + 127) / 128;

    // --- layer 1 ---
    k_agg<<<aggBlocks, 256>>>(p_x);
    k_gemm_tc<<<gemmBlocks, 256, GEMM_SMEM>>>(p_x, p_m, p_wh, b1,
                                              p_h1, nullptr, N_NODES, 256);
    // --- layer 2 ---
    k_agg<<<aggBlocks, 256>>>(p_h1);
    k_gemm_tc<<<gemmBlocks, 256, GEMM_SMEM>>>(p_h1, p_m, p_wh + 256 * D, b2,
                                              p_h2, nullptr, N_NODES, 256);
    // --- layer 3 + predictor (fused via composed weights; gridDim.y=2) ---
    k_agg<<<aggBlocks, 256>>>(p_h2);
    k_gemm_tc<<<dim3(gemmBlocks, 2), 256, GEMM_SMEM>>>(
                                              p_h2, p_m, p_wh + 512 * D, p_bc,
                                              p_pa16, p_pb16, N_NODES, 256);

    // --- edge scores (+ restores cnt/ready invariant) ---
    k_edge<<<(2 * N_EDGES * 16 + 255) / 256, 256>>>(src, dst, nsrc, ndst, Wp2, bp2, out);
}